// round 6
// baseline (speedup 1.0000x reference)
#include <cuda_runtime.h>
#include <math_constants.h>

#define NB 256
#define NQ 1000
#define NC 80
#define NN 80000          // NQ * NC per batch
#define TOPK 300
#define TT 1024           // thresh kernel threads
#define ST 256            // stream kernel threads
#define NCH 20            // chunks per batch
#define SCH 4096          // elements per chunk
#define CHCAP 512         // per-chunk survivor slice capacity
#define SCAP 4096         // smem candidate buffer entries (u64)
#define LISTCAP 2048
#define HBINS 2048
#define TSAMP 64          // sample-rank target for streaming threshold
#define TSEL 384          // final selection rank (slack over 300)

// ---------------- global scratch (static __device__, no allocs) ----------------
__device__ unsigned long long g_bufc[NB][NCH][CHCAP];   // per-chunk survivor slices
__device__ int g_cntc[NB][NCH];                         // per-chunk counts (plain stores)
__device__ int g_done[NB][32];                          // padded arrive counters
__device__ float g_thrf[NB];

// ---------- monotone float<->uint mapping ----------
__device__ __forceinline__ unsigned flipf(unsigned b) {
    return (b & 0x80000000u) ? ~b : (b | 0x80000000u);
}
__device__ __forceinline__ unsigned unflipf(unsigned u) {
    return (u & 0x80000000u) ? (u & 0x7FFFFFFFu) : ~u;
}

// ---------- sigmoid matching XLA: logistic(x) = 0.5 + 0.5*tanh(0.5*x) ----------
__device__ __forceinline__ float sigmoid_ref(float x) {
    float hx = __fmul_rn(0.5f, x);
    float ax = fabsf(hx);
    float xc = fminf(fmaxf(hx, -9.0f), 9.0f);
    float x2 = __fmul_rn(xc, xc);
    float p = -2.76076847742355e-16f;
    p = fmaf(x2, p, 2.00018790482477e-13f);
    p = fmaf(x2, p, -8.60467152213735e-11f);
    p = fmaf(x2, p, 5.12229709037114e-08f);
    p = fmaf(x2, p, 1.48572235717979e-05f);
    p = fmaf(x2, p, 6.37261928875436e-04f);
    p = fmaf(x2, p, 4.89352455891786e-03f);
    p = __fmul_rn(xc, p);
    float q = 1.19825839466702e-06f;
    q = fmaf(x2, q, 1.18534705686654e-04f);
    q = fmaf(x2, q, 2.26843463243900e-03f);
    q = fmaf(x2, q, 4.89352518554385e-03f);
    float t = __fdiv_rn(p, q);
    t = (ax < 4e-4f) ? hx : t;
    return __fadd_rn(__fmul_rn(0.5f, t), 0.5f);
}

// ================= 1024-thread suffix scan (thresh kernel) =================
__device__ __forceinline__ void suffix_scan1024(unsigned* hist, unsigned* wsum) {
    const int tid = threadIdx.x;
    const int lane = tid & 31;
    const int w = tid >> 5;
    unsigned x0 = hist[2047 - 2 * tid];
    unsigned x1 = hist[2046 - 2 * tid];
    unsigned s = x0 + x1;
    unsigned incl = s;
    #pragma unroll
    for (int o = 1; o < 32; o <<= 1) {
        unsigned v = __shfl_up_sync(0xFFFFFFFFu, incl, o);
        if (lane >= o) incl += v;
    }
    if (lane == 31) wsum[w] = incl;
    unsigned excl_lane = incl - s;
    __syncthreads();
    if (tid < 32) {
        unsigned v = wsum[tid];
        unsigned wincl = v;
        #pragma unroll
        for (int o = 1; o < 32; o <<= 1) {
            unsigned t2 = __shfl_up_sync(0xFFFFFFFFu, wincl, o);
            if (tid >= o) wincl += t2;
        }
        wsum[tid] = wincl - v;
    }
    __syncthreads();
    unsigned excl = wsum[w] + excl_lane;
    hist[2047 - 2 * tid] = excl + x0;
    hist[2046 - 2 * tid] = excl + x0 + x1;
    __syncthreads();
}

// ================= 256-thread suffix scan over 2048 bins =================
// thread t owns bins [2040-8t .. 2047-8t]; ascending tid == descending bins.
__device__ __forceinline__ void suffix_scan256(unsigned* hist, unsigned* wsum8) {
    const int tid = threadIdx.x;
    const int lane = tid & 31;
    const int w = tid >> 5;
    const int base = HBINS - 8 - 8 * tid;
    unsigned x[8];
    #pragma unroll
    for (int j = 0; j < 8; ++j) x[j] = hist[base + j];
    unsigned tot = x[0] + x[1] + x[2] + x[3] + x[4] + x[5] + x[6] + x[7];
    unsigned incl = tot;
    #pragma unroll
    for (int o = 1; o < 32; o <<= 1) {
        unsigned t2 = __shfl_up_sync(0xFFFFFFFFu, incl, o);
        if (lane >= o) incl += t2;
    }
    if (lane == 31) wsum8[w] = incl;
    unsigned excl = incl - tot;
    __syncthreads();
    if (tid < 8) {
        unsigned v = wsum8[tid];
        unsigned wincl = v;
        #pragma unroll
        for (int o = 1; o < 8; o <<= 1) {
            unsigned t2 = __shfl_up_sync(0xFFu, wincl, o);
            if (tid >= o) wincl += t2;
        }
        wsum8[tid] = wincl - v;
    }
    __syncthreads();
    unsigned carry = wsum8[w] + excl;
    unsigned run = carry;
    #pragma unroll
    for (int j = 7; j >= 0; --j) { run += x[j]; hist[base + j] = run; }
    __syncthreads();
}

// ---------- smem append (fallback path only), 256-thread ----------
__device__ __forceinline__ void append_smem256(unsigned long long* buf, int* cnt,
                                               unsigned ub, unsigned idx) {
    unsigned long long key = ((unsigned long long)ub << 32) | idx;
    unsigned mask = __activemask();
    int lane = threadIdx.x & 31;
    int leader = __ffs(mask) - 1;
    int pos = 0;
    if (lane == leader) pos = atomicAdd(cnt, __popc(mask));
    pos = __shfl_sync(mask, pos, leader) + __popc(mask & ((1u << lane) - 1u));
    if (pos < SCAP) buf[pos] = key;
}

// ---------- 256-thread histogram radix-select ----------
// sc[0]=B, sc[1]=B2, sc[2]=refined, sc[3]=gathered, sc[4]=nAbove
__device__ void run_select256(unsigned long long* buf, unsigned long long* lst,
                              unsigned* hist, unsigned* wsum8, int* sc, int n, int target) {
    const int tid = threadIdx.x;
    if (n <= target) {
        if (tid == 0) { sc[0] = 0; sc[1] = 0; sc[2] = 0; sc[3] = n; }
        __syncthreads();
        for (int i = tid; i < n; i += ST) lst[i] = buf[i];
        __syncthreads();
        return;
    }
    for (int i = tid; i < HBINS; i += ST) hist[i] = 0;
    __syncthreads();
    for (int i = tid; i < n; i += ST)
        atomicAdd(&hist[(unsigned)(buf[i] >> 53)], 1u);
    __syncthreads();
    suffix_scan256(hist, wsum8);
    for (int i = tid * 8; i < tid * 8 + 8; ++i) {
        unsigned s = hist[i];
        unsigned sn = (i + 1 < HBINS) ? hist[i + 1] : 0u;
        if (s >= (unsigned)target && sn < (unsigned)target) { sc[0] = i; sc[4] = (int)sn; }
    }
    if (tid == 0) { sc[2] = 0; sc[3] = 0; }
    __syncthreads();
    const int B = sc[0];
    const int nAbove = sc[4];
    const int selcount = (int)hist[B];
    int refined = 0, B2 = 0;
    if (selcount > 1024) {                      // refine boundary bin on next 11 bits
        __syncthreads();
        for (int i = tid; i < HBINS; i += ST) hist[i] = 0;
        __syncthreads();
        for (int i = tid; i < n; i += ST) {
            unsigned long long k = buf[i];
            if ((unsigned)(k >> 53) == (unsigned)B)
                atomicAdd(&hist[(unsigned)(k >> 42) & 0x7FFu], 1u);
        }
        __syncthreads();
        suffix_scan256(hist, wsum8);
        int extra = target - nAbove;
        for (int i = tid * 8; i < tid * 8 + 8; ++i) {
            unsigned s = hist[i];
            unsigned sn = (i + 1 < HBINS) ? hist[i + 1] : 0u;
            if (s >= (unsigned)extra && sn < (unsigned)extra) sc[1] = i;
        }
        if (tid == 0) sc[2] = 1;
        __syncthreads();
        refined = 1;
        B2 = sc[1];
    }
    for (int i = tid; i < n; i += ST) {
        unsigned long long k = buf[i];
        unsigned bin = (unsigned)(k >> 53);
        bool sel = (bin > (unsigned)B) ||
                   (bin == (unsigned)B &&
                    (!refined || (((unsigned)(k >> 42) & 0x7FFu) >= (unsigned)B2)));
        if (sel) {
            int p = atomicAdd(&sc[3], 1);
            if (p < LISTCAP) lst[p] = k;
        }
    }
    __syncthreads();
}

// ================= kernel A: per-batch threshold from 4096-sample =================
extern "C" __global__ void __launch_bounds__(TT)
thresh_kernel(const float* __restrict__ logits) {
    __shared__ unsigned hist[HBINS];
    __shared__ unsigned wsum[32];
    __shared__ int s_bin;
    const int tid = threadIdx.x;
    const int b = blockIdx.x;
    const float* Lp = logits + (size_t)b * NN;

    hist[tid] = 0; hist[tid + TT] = 0;
    if (tid == 0) { s_bin = 0; g_done[b][0] = 0; }
    __syncthreads();
    {
        float4 v = *reinterpret_cast<const float4*>(Lp + tid * 4);
        atomicAdd(&hist[flipf(__float_as_uint(v.x)) >> 21], 1u);
        atomicAdd(&hist[flipf(__float_as_uint(v.y)) >> 21], 1u);
        atomicAdd(&hist[flipf(__float_as_uint(v.z)) >> 21], 1u);
        atomicAdd(&hist[flipf(__float_as_uint(v.w)) >> 21], 1u);
    }
    __syncthreads();
    suffix_scan1024(hist, wsum);
    {
        unsigned s0 = hist[tid];
        unsigned s0n = (tid + 1 < HBINS) ? hist[tid + 1] : 0u;
        if (s0 >= TSAMP && s0n < TSAMP) s_bin = tid;
        unsigned s1 = hist[tid + TT];
        unsigned s1n = (tid + TT + 1 < HBINS) ? hist[tid + TT + 1] : 0u;
        if (s1 >= TSAMP && s1n < TSAMP) s_bin = tid + TT;
    }
    __syncthreads();
    if (tid == 0) {
        g_thrf[b] = (s_bin == 0) ? -CUDART_INF_F
                                 : __uint_as_float(unflipf((unsigned)s_bin << 21));
    }
}

// ================= kernel B: stream + (last CTA per batch) select =================
extern "C" __global__ void __launch_bounds__(ST)
stream_kernel(const float* __restrict__ logits,
              const float* __restrict__ boxes,
              float* __restrict__ out) {
    extern __shared__ unsigned char smem_raw[];
    unsigned long long* buf = reinterpret_cast<unsigned long long*>(smem_raw); // SCAP
    unsigned long long* lst = buf + SCAP;                                      // LISTCAP
    unsigned* hist = reinterpret_cast<unsigned*>(lst + LISTCAP);               // HBINS
    unsigned long long* skeys = buf;     // staging aliases buf (disjoint in time)
    __shared__ unsigned wsum8[8];
    __shared__ int s_cnt;
    __shared__ int sc[5];
    __shared__ int s_off[NCH + 1];
    __shared__ int s_bad;
    __shared__ int s_last;

    const int tid = threadIdx.x;
    const int lane = tid & 31;
    const int chunk = blockIdx.x;          // 0..NCH-1
    const int b = blockIdx.y;              // 0..NB-1
    const float* Lp = logits + (size_t)b * NN + chunk * SCH;
    const int rem = NN - chunk * SCH;
    const float thr = g_thrf[b];

    if (tid == 0) s_cnt = 0;
    __syncthreads();

    // ---- 4 independent float4 loads up front (MLP) ----
    float4 v[4];
    bool ok[4];
    #pragma unroll
    for (int i = 0; i < 4; ++i) {
        int off = i * (ST * 4) + tid * 4;
        ok[i] = off < rem;
        if (ok[i]) v[i] = __ldcs(reinterpret_cast<const float4*>(Lp + off));
    }

    // ---- per-thread collect + one warp-aggregated smem atomic per group ----
    #pragma unroll
    for (int i = 0; i < 4; ++i) {
        unsigned long long loc[4];
        int nl = 0;
        if (ok[i]) {
            int base = chunk * SCH + i * (ST * 4) + tid * 4;
            float4 w = v[i];
            if (w.x >= thr) loc[nl++] = ((unsigned long long)flipf(__float_as_uint(w.x)) << 32) | (unsigned)base;
            if (w.y >= thr) loc[nl++] = ((unsigned long long)flipf(__float_as_uint(w.y)) << 32) | (unsigned)(base + 1);
            if (w.z >= thr) loc[nl++] = ((unsigned long long)flipf(__float_as_uint(w.z)) << 32) | (unsigned)(base + 2);
            if (w.w >= thr) loc[nl++] = ((unsigned long long)flipf(__float_as_uint(w.w)) << 32) | (unsigned)(base + 3);
        }
        int incl = nl;
        #pragma unroll
        for (int o = 1; o < 32; o <<= 1) {
            int t2 = __shfl_up_sync(0xFFFFFFFFu, incl, o);
            if (lane >= o) incl += t2;
        }
        int wtot = __shfl_sync(0xFFFFFFFFu, incl, 31);
        int wbase = 0;
        if (lane == 0 && wtot > 0) wbase = atomicAdd(&s_cnt, wtot);
        wbase = __shfl_sync(0xFFFFFFFFu, wbase, 0);
        int p = wbase + incl - nl;
        for (int j = 0; j < nl; ++j)
            if (p + j < CHCAP) skeys[p + j] = loc[j];
    }
    __syncthreads();
    const int cn = s_cnt;
    for (int i = tid; i < min(cn, CHCAP); i += ST)
        g_bufc[b][chunk][i] = skeys[i];
    if (tid == 0) g_cntc[b][chunk] = cn;           // raw count (overflow detect)
    __threadfence();
    __syncthreads();
    if (tid == 0) {
        int prev = atomicAdd(&g_done[b][0], 1);
        s_last = (prev == NCH - 1);
    }
    __syncthreads();
    if (!s_last) return;

    // ================= last CTA of batch: selection =================
    if (tid < NCH) s_off[tid] = *((volatile int*)&g_cntc[b][tid]);
    __syncthreads();
    if (tid == 0) {
        int acc = 0, bd = 0;
        for (int s2 = 0; s2 < NCH; ++s2) {
            int c = s_off[s2];
            if (c > CHCAP) { bd = 1; c = CHCAP; }
            s_off[s2] = acc;
            acc += c;
        }
        s_off[NCH] = acc;
        s_bad = bd || (acc > SCAP);
    }
    __syncthreads();
    int m = s_off[NCH];

    if (!s_bad) {
        // gather all slices into compact smem buffer (coalesced per slice)
        for (int s2 = 0; s2 < NCH; ++s2) {
            int o0 = s_off[s2];
            int len = s_off[s2 + 1] - o0;
            for (int i = tid; i < len; i += ST)
                buf[o0 + i] = g_bufc[b][s2][i];
        }
        __syncthreads();
    } else {
        // ---- overflow fallback: adaptive restream of whole batch (never taken) ----
        if (tid == 0) s_cnt = 0;
        __syncthreads();
        unsigned thr2 = 0u;
        const float* Lb = logits + (size_t)b * NN;
        const int ngr = (NN + ST * 4 - 1) / (ST * 4);
        for (int g = 0; g < ngr; ++g) {
            int base = g * (ST * 4) + tid * 4;
            if (base < NN) {
                float4 w = *reinterpret_cast<const float4*>(Lb + base);
                unsigned ub[4] = {flipf(__float_as_uint(w.x)), flipf(__float_as_uint(w.y)),
                                  flipf(__float_as_uint(w.z)), flipf(__float_as_uint(w.w))};
                #pragma unroll
                for (int e = 0; e < 4; ++e)
                    if (ub[e] >= thr2) append_smem256(buf, &s_cnt, ub[e], base + e);
            }
            __syncthreads();
            if (s_cnt > SCAP - ST * 4) {
                run_select256(buf, lst, hist, wsum8, sc, min(s_cnt, SCAP), TSEL);
                int mm = min(sc[3], LISTCAP);
                for (int i = tid; i < mm; i += ST) buf[i] = lst[i];
                __syncthreads();
                if (tid == 0) s_cnt = mm;
                __syncthreads();
                thr2 = sc[2] ? (((unsigned)sc[0] << 21) | ((unsigned)sc[1] << 10))
                             : ((unsigned)sc[0] << 21);
            }
        }
        m = min(s_cnt, SCAP);
    }

    // prune to ~TSEL best
    run_select256(buf, lst, hist, wsum8, sc, m, TSEL);
    int msel = min(sc[3], LISTCAP);

    // sigmoid rank keys: score desc, index asc
    for (int i = tid; i < msel; i += ST) {
        unsigned long long k = lst[i];
        unsigned u = (unsigned)(k >> 32);
        unsigned idx = (unsigned)k;
        float s = sigmoid_ref(__uint_as_float(unflipf(u)));
        lst[i] = ((unsigned long long)__float_as_uint(s) << 32) |
                 (unsigned)(0xFFFFFFFFu - idx);
    }
    __syncthreads();

    // exact rank by counting; write outputs for rank < TOPK
    for (int i = tid; i < msel; i += ST) {
        unsigned long long k = lst[i];
        int r = 0;
        for (int j = 0; j < msel; ++j) r += (lst[j] > k) ? 1 : 0;
        if (r < TOPK) {
            unsigned idx = 0xFFFFFFFFu - (unsigned)k;
            float s = __uint_as_float((unsigned)(k >> 32));
            int q = (int)(idx / NC);
            int c = (int)(idx - (unsigned)q * NC);
            size_t o = (size_t)b * TOPK + (size_t)r;
            out[o] = (float)c;                                   // labels
            float4 bx = *reinterpret_cast<const float4*>(
                boxes + ((size_t)b * NQ + (size_t)q) * 4);
            float4 xy;
            xy.x = bx.x - 0.5f * bx.z;
            xy.y = bx.y - 0.5f * bx.w;
            xy.z = bx.x + 0.5f * bx.z;
            xy.w = bx.y + 0.5f * bx.w;
            *reinterpret_cast<float4*>(out + (size_t)NB * TOPK + o * 4) = xy;  // boxes
            out[(size_t)NB * TOPK * 5 + o] = s;                  // scores
        }
    }
}

extern "C" void kernel_launch(void* const* d_in, const int* in_sizes, int n_in,
                              void* d_out, int out_size) {
    const float* logits = (const float*)d_in[0];
    const float* boxes = (const float*)d_in[1];
    size_t smem = (size_t)SCAP * 8 + (size_t)LISTCAP * 8 + (size_t)HBINS * 4; // 57344 B
    cudaFuncSetAttribute(stream_kernel,
                         cudaFuncAttributeMaxDynamicSharedMemorySize, (int)smem);
    thresh_kernel<<<NB, TT>>>(logits);
    dim3 sg(NCH, NB, 1);
    stream_kernel<<<sg, ST, smem>>>(logits, boxes, (float*)d_out);
}

// round 7
// speedup vs baseline: 1.4662x; 1.4662x over previous
#include <cuda_runtime.h>
#include <math_constants.h>

#define NB 256
#define NQ 1000
#define NC 80
#define NN 80000          // NQ * NC per batch
#define TOPK 300
#define TT 1024           // thresh kernel threads
#define ST 256            // stream/select kernel threads
#define NCH 20            // chunks per batch
#define SCH 4096          // elements per chunk
#define CHCAP 512         // per-chunk survivor slice capacity
#define SCAP 4096         // smem candidate buffer entries (u64)
#define LISTCAP 2048
#define HBINS 2048
#define TSAMP 64          // sample-rank target for streaming threshold
#define TSEL 384          // final selection rank (slack over 300)

// ---------------- global scratch (static __device__, no allocs) ----------------
__device__ unsigned long long g_bufc[NB][NCH][CHCAP];   // per-chunk survivor slices
__device__ int g_cntc[NB][NCH];                         // per-chunk counts (plain stores)
__device__ float g_thrf[NB];

// ---------- monotone float<->uint mapping ----------
__device__ __forceinline__ unsigned flipf(unsigned b) {
    return (b & 0x80000000u) ? ~b : (b | 0x80000000u);
}
__device__ __forceinline__ unsigned unflipf(unsigned u) {
    return (u & 0x80000000u) ? (u & 0x7FFFFFFFu) : ~u;
}

// ---------- sigmoid matching XLA: logistic(x) = 0.5 + 0.5*tanh(0.5*x) ----------
__device__ __forceinline__ float sigmoid_ref(float x) {
    float hx = __fmul_rn(0.5f, x);
    float ax = fabsf(hx);
    float xc = fminf(fmaxf(hx, -9.0f), 9.0f);
    float x2 = __fmul_rn(xc, xc);
    float p = -2.76076847742355e-16f;
    p = fmaf(x2, p, 2.00018790482477e-13f);
    p = fmaf(x2, p, -8.60467152213735e-11f);
    p = fmaf(x2, p, 5.12229709037114e-08f);
    p = fmaf(x2, p, 1.48572235717979e-05f);
    p = fmaf(x2, p, 6.37261928875436e-04f);
    p = fmaf(x2, p, 4.89352455891786e-03f);
    p = __fmul_rn(xc, p);
    float q = 1.19825839466702e-06f;
    q = fmaf(x2, q, 1.18534705686654e-04f);
    q = fmaf(x2, q, 2.26843463243900e-03f);
    q = fmaf(x2, q, 4.89352518554385e-03f);
    float t = __fdiv_rn(p, q);
    t = (ax < 4e-4f) ? hx : t;
    return __fadd_rn(__fmul_rn(0.5f, t), 0.5f);
}

// ================= 1024-thread suffix scan (thresh kernel) =================
__device__ __forceinline__ void suffix_scan1024(unsigned* hist, unsigned* wsum) {
    const int tid = threadIdx.x;
    const int lane = tid & 31;
    const int w = tid >> 5;
    unsigned x0 = hist[2047 - 2 * tid];
    unsigned x1 = hist[2046 - 2 * tid];
    unsigned s = x0 + x1;
    unsigned incl = s;
    #pragma unroll
    for (int o = 1; o < 32; o <<= 1) {
        unsigned v = __shfl_up_sync(0xFFFFFFFFu, incl, o);
        if (lane >= o) incl += v;
    }
    if (lane == 31) wsum[w] = incl;
    unsigned excl_lane = incl - s;
    __syncthreads();
    if (tid < 32) {
        unsigned v = wsum[tid];
        unsigned wincl = v;
        #pragma unroll
        for (int o = 1; o < 32; o <<= 1) {
            unsigned t2 = __shfl_up_sync(0xFFFFFFFFu, wincl, o);
            if (tid >= o) wincl += t2;
        }
        wsum[tid] = wincl - v;
    }
    __syncthreads();
    unsigned excl = wsum[w] + excl_lane;
    hist[2047 - 2 * tid] = excl + x0;
    hist[2046 - 2 * tid] = excl + x0 + x1;
    __syncthreads();
}

// ================= 256-thread suffix scan over 2048 bins =================
__device__ __forceinline__ void suffix_scan256(unsigned* hist, unsigned* wsum8) {
    const int tid = threadIdx.x;
    const int lane = tid & 31;
    const int w = tid >> 5;
    const int base = HBINS - 8 - 8 * tid;
    unsigned x[8];
    #pragma unroll
    for (int j = 0; j < 8; ++j) x[j] = hist[base + j];
    unsigned tot = x[0] + x[1] + x[2] + x[3] + x[4] + x[5] + x[6] + x[7];
    unsigned incl = tot;
    #pragma unroll
    for (int o = 1; o < 32; o <<= 1) {
        unsigned t2 = __shfl_up_sync(0xFFFFFFFFu, incl, o);
        if (lane >= o) incl += t2;
    }
    if (lane == 31) wsum8[w] = incl;
    unsigned excl = incl - tot;
    __syncthreads();
    if (tid < 8) {
        unsigned v = wsum8[tid];
        unsigned wincl = v;
        #pragma unroll
        for (int o = 1; o < 8; o <<= 1) {
            unsigned t2 = __shfl_up_sync(0xFFu, wincl, o);
            if (tid >= o) wincl += t2;
        }
        wsum8[tid] = wincl - v;
    }
    __syncthreads();
    unsigned carry = wsum8[w] + excl;
    unsigned run = carry;
    #pragma unroll
    for (int j = 7; j >= 0; --j) { run += x[j]; hist[base + j] = run; }
    __syncthreads();
}

// ---------- smem append (fallback path only), 256-thread ----------
__device__ __forceinline__ void append_smem256(unsigned long long* buf, int* cnt,
                                               unsigned ub, unsigned idx) {
    unsigned long long key = ((unsigned long long)ub << 32) | idx;
    unsigned mask = __activemask();
    int lane = threadIdx.x & 31;
    int leader = __ffs(mask) - 1;
    int pos = 0;
    if (lane == leader) pos = atomicAdd(cnt, __popc(mask));
    pos = __shfl_sync(mask, pos, leader) + __popc(mask & ((1u << lane) - 1u));
    if (pos < SCAP) buf[pos] = key;
}

// ---------- 256-thread histogram radix-select ----------
__device__ void run_select256(unsigned long long* buf, unsigned long long* lst,
                              unsigned* hist, unsigned* wsum8, int* sc, int n, int target) {
    const int tid = threadIdx.x;
    if (n <= target) {
        if (tid == 0) { sc[0] = 0; sc[1] = 0; sc[2] = 0; sc[3] = n; }
        __syncthreads();
        for (int i = tid; i < n; i += ST) lst[i] = buf[i];
        __syncthreads();
        return;
    }
    for (int i = tid; i < HBINS; i += ST) hist[i] = 0;
    __syncthreads();
    for (int i = tid; i < n; i += ST)
        atomicAdd(&hist[(unsigned)(buf[i] >> 53)], 1u);
    __syncthreads();
    suffix_scan256(hist, wsum8);
    for (int i = tid * 8; i < tid * 8 + 8; ++i) {
        unsigned s = hist[i];
        unsigned sn = (i + 1 < HBINS) ? hist[i + 1] : 0u;
        if (s >= (unsigned)target && sn < (unsigned)target) { sc[0] = i; sc[4] = (int)sn; }
    }
    if (tid == 0) { sc[2] = 0; sc[3] = 0; }
    __syncthreads();
    const int B = sc[0];
    const int nAbove = sc[4];
    const int selcount = (int)hist[B];
    int refined = 0, B2 = 0;
    if (selcount > 1024) {
        __syncthreads();
        for (int i = tid; i < HBINS; i += ST) hist[i] = 0;
        __syncthreads();
        for (int i = tid; i < n; i += ST) {
            unsigned long long k = buf[i];
            if ((unsigned)(k >> 53) == (unsigned)B)
                atomicAdd(&hist[(unsigned)(k >> 42) & 0x7FFu], 1u);
        }
        __syncthreads();
        suffix_scan256(hist, wsum8);
        int extra = target - nAbove;
        for (int i = tid * 8; i < tid * 8 + 8; ++i) {
            unsigned s = hist[i];
            unsigned sn = (i + 1 < HBINS) ? hist[i + 1] : 0u;
            if (s >= (unsigned)extra && sn < (unsigned)extra) sc[1] = i;
        }
        if (tid == 0) sc[2] = 1;
        __syncthreads();
        refined = 1;
        B2 = sc[1];
    }
    for (int i = tid; i < n; i += ST) {
        unsigned long long k = buf[i];
        unsigned bin = (unsigned)(k >> 53);
        bool sel = (bin > (unsigned)B) ||
                   (bin == (unsigned)B &&
                    (!refined || (((unsigned)(k >> 42) & 0x7FFu) >= (unsigned)B2)));
        if (sel) {
            int p = atomicAdd(&sc[3], 1);
            if (p < LISTCAP) lst[p] = k;
        }
    }
    __syncthreads();
}

// ================= kernel A: per-batch threshold from 4096-sample =================
extern "C" __global__ void __launch_bounds__(TT)
thresh_kernel(const float* __restrict__ logits) {
    __shared__ unsigned hist[HBINS];
    __shared__ unsigned wsum[32];
    __shared__ int s_bin;
    const int tid = threadIdx.x;
    const int b = blockIdx.x;
    const float* Lp = logits + (size_t)b * NN;

    hist[tid] = 0; hist[tid + TT] = 0;
    if (tid == 0) s_bin = 0;
    __syncthreads();
    {
        float4 v = *reinterpret_cast<const float4*>(Lp + tid * 4);
        atomicAdd(&hist[flipf(__float_as_uint(v.x)) >> 21], 1u);
        atomicAdd(&hist[flipf(__float_as_uint(v.y)) >> 21], 1u);
        atomicAdd(&hist[flipf(__float_as_uint(v.z)) >> 21], 1u);
        atomicAdd(&hist[flipf(__float_as_uint(v.w)) >> 21], 1u);
    }
    __syncthreads();
    suffix_scan1024(hist, wsum);
    {
        unsigned s0 = hist[tid];
        unsigned s0n = (tid + 1 < HBINS) ? hist[tid + 1] : 0u;
        if (s0 >= TSAMP && s0n < TSAMP) s_bin = tid;
        unsigned s1 = hist[tid + TT];
        unsigned s1n = (tid + TT + 1 < HBINS) ? hist[tid + TT + 1] : 0u;
        if (s1 >= TSAMP && s1n < TSAMP) s_bin = tid + TT;
    }
    __syncthreads();
    if (tid == 0) {
        g_thrf[b] = (s_bin == 0) ? -CUDART_INF_F
                                 : __uint_as_float(unflipf((unsigned)s_bin << 21));
    }
}

// ================= kernel B: lean full-bandwidth filter stream =================
// Only 4.1 KB smem -> 8 CTAs/SM (thread-bound occupancy).
extern "C" __global__ void __launch_bounds__(ST)
stream_kernel(const float* __restrict__ logits) {
    __shared__ unsigned long long skeys[CHCAP];
    __shared__ int s_cnt;

    const int tid = threadIdx.x;
    const int lane = tid & 31;
    const int chunk = blockIdx.x;          // 0..NCH-1
    const int b = blockIdx.y;              // 0..NB-1
    const float* Lp = logits + (size_t)b * NN + chunk * SCH;
    const int rem = NN - chunk * SCH;
    const float thr = g_thrf[b];

    if (tid == 0) s_cnt = 0;
    __syncthreads();

    // ---- 4 independent float4 loads up front (MLP) ----
    float4 v[4];
    bool ok[4];
    #pragma unroll
    for (int i = 0; i < 4; ++i) {
        int off = i * (ST * 4) + tid * 4;
        ok[i] = off < rem;
        if (ok[i]) v[i] = __ldcs(reinterpret_cast<const float4*>(Lp + off));
    }

    // ---- per-thread collect + one warp-aggregated smem atomic per group ----
    #pragma unroll
    for (int i = 0; i < 4; ++i) {
        unsigned long long loc[4];
        int nl = 0;
        if (ok[i]) {
            int base = chunk * SCH + i * (ST * 4) + tid * 4;
            float4 w = v[i];
            if (w.x >= thr) loc[nl++] = ((unsigned long long)flipf(__float_as_uint(w.x)) << 32) | (unsigned)base;
            if (w.y >= thr) loc[nl++] = ((unsigned long long)flipf(__float_as_uint(w.y)) << 32) | (unsigned)(base + 1);
            if (w.z >= thr) loc[nl++] = ((unsigned long long)flipf(__float_as_uint(w.z)) << 32) | (unsigned)(base + 2);
            if (w.w >= thr) loc[nl++] = ((unsigned long long)flipf(__float_as_uint(w.w)) << 32) | (unsigned)(base + 3);
        }
        int incl = nl;
        #pragma unroll
        for (int o = 1; o < 32; o <<= 1) {
            int t2 = __shfl_up_sync(0xFFFFFFFFu, incl, o);
            if (lane >= o) incl += t2;
        }
        int wtot = __shfl_sync(0xFFFFFFFFu, incl, 31);
        int wbase = 0;
        if (lane == 0 && wtot > 0) wbase = atomicAdd(&s_cnt, wtot);
        wbase = __shfl_sync(0xFFFFFFFFu, wbase, 0);
        int p = wbase + incl - nl;
        for (int j = 0; j < nl; ++j)
            if (p + j < CHCAP) skeys[p + j] = loc[j];
    }
    __syncthreads();
    const int cn = s_cnt;
    for (int i = tid; i < min(cn, CHCAP); i += ST)
        g_bufc[b][chunk][i] = skeys[i];
    if (tid == 0) g_cntc[b][chunk] = cn;      // raw count (overflow detect)
}

// ================= kernel C: gather + select + sigmoid + rank + write =================
extern "C" __global__ void __launch_bounds__(ST)
select_kernel(const float* __restrict__ logits,
              const float* __restrict__ boxes,
              float* __restrict__ out) {
    extern __shared__ unsigned char smem_raw[];
    unsigned long long* buf = reinterpret_cast<unsigned long long*>(smem_raw); // SCAP
    unsigned long long* lst = buf + SCAP;                                      // LISTCAP
    unsigned* hist = reinterpret_cast<unsigned*>(lst + LISTCAP);               // HBINS
    __shared__ unsigned wsum8[8];
    __shared__ int s_cnt;
    __shared__ int sc[5];
    __shared__ int s_off[NCH + 1];
    __shared__ int s_bad;

    const int tid = threadIdx.x;
    const int b = blockIdx.x;

    if (tid < NCH) s_off[tid] = g_cntc[b][tid];
    __syncthreads();
    if (tid == 0) {
        int acc = 0, bd = 0;
        for (int s2 = 0; s2 < NCH; ++s2) {
            int c = s_off[s2];
            if (c > CHCAP) { bd = 1; c = CHCAP; }
            s_off[s2] = acc;
            acc += c;
        }
        s_off[NCH] = acc;
        s_bad = bd || (acc > SCAP);
    }
    __syncthreads();
    int m = s_off[NCH];

    if (!s_bad) {
        for (int s2 = 0; s2 < NCH; ++s2) {
            int o0 = s_off[s2];
            int len = s_off[s2 + 1] - o0;
            for (int i = tid; i < len; i += ST)
                buf[o0 + i] = g_bufc[b][s2][i];
        }
        __syncthreads();
    } else {
        // ---- overflow fallback: adaptive restream of whole batch (never taken) ----
        if (tid == 0) s_cnt = 0;
        __syncthreads();
        unsigned thr2 = 0u;
        const float* Lb = logits + (size_t)b * NN;
        const int ngr = (NN + ST * 4 - 1) / (ST * 4);
        for (int g = 0; g < ngr; ++g) {
            int base = g * (ST * 4) + tid * 4;
            if (base < NN) {
                float4 w = *reinterpret_cast<const float4*>(Lb + base);
                unsigned ub[4] = {flipf(__float_as_uint(w.x)), flipf(__float_as_uint(w.y)),
                                  flipf(__float_as_uint(w.z)), flipf(__float_as_uint(w.w))};
                #pragma unroll
                for (int e = 0; e < 4; ++e)
                    if (ub[e] >= thr2) append_smem256(buf, &s_cnt, ub[e], base + e);
            }
            __syncthreads();
            if (s_cnt > SCAP - ST * 4) {
                run_select256(buf, lst, hist, wsum8, sc, min(s_cnt, SCAP), TSEL);
                int mm = min(sc[3], LISTCAP);
                for (int i = tid; i < mm; i += ST) buf[i] = lst[i];
                __syncthreads();
                if (tid == 0) s_cnt = mm;
                __syncthreads();
                thr2 = sc[2] ? (((unsigned)sc[0] << 21) | ((unsigned)sc[1] << 10))
                             : ((unsigned)sc[0] << 21);
            }
        }
        m = min(s_cnt, SCAP);
    }

    // prune to ~TSEL best
    run_select256(buf, lst, hist, wsum8, sc, m, TSEL);
    int msel = min(sc[3], LISTCAP);

    // sigmoid rank keys: score desc, index asc
    for (int i = tid; i < msel; i += ST) {
        unsigned long long k = lst[i];
        unsigned u = (unsigned)(k >> 32);
        unsigned idx = (unsigned)k;
        float s = sigmoid_ref(__uint_as_float(unflipf(u)));
        lst[i] = ((unsigned long long)__float_as_uint(s) << 32) |
                 (unsigned)(0xFFFFFFFFu - idx);
    }
    __syncthreads();

    // exact rank by counting; write outputs for rank < TOPK
    for (int i = tid; i < msel; i += ST) {
        unsigned long long k = lst[i];
        int r = 0;
        for (int j = 0; j < msel; ++j) r += (lst[j] > k) ? 1 : 0;
        if (r < TOPK) {
            unsigned idx = 0xFFFFFFFFu - (unsigned)k;
            float s = __uint_as_float((unsigned)(k >> 32));
            int q = (int)(idx / NC);
            int c = (int)(idx - (unsigned)q * NC);
            size_t o = (size_t)b * TOPK + (size_t)r;
            out[o] = (float)c;                                   // labels
            float4 bx = *reinterpret_cast<const float4*>(
                boxes + ((size_t)b * NQ + (size_t)q) * 4);
            float4 xy;
            xy.x = bx.x - 0.5f * bx.z;
            xy.y = bx.y - 0.5f * bx.w;
            xy.z = bx.x + 0.5f * bx.z;
            xy.w = bx.y + 0.5f * bx.w;
            *reinterpret_cast<float4*>(out + (size_t)NB * TOPK + o * 4) = xy;  // boxes
            out[(size_t)NB * TOPK * 5 + o] = s;                  // scores
        }
    }
}

extern "C" void kernel_launch(void* const* d_in, const int* in_sizes, int n_in,
                              void* d_out, int out_size) {
    const float* logits = (const float*)d_in[0];
    const float* boxes = (const float*)d_in[1];
    size_t smem = (size_t)SCAP * 8 + (size_t)LISTCAP * 8 + (size_t)HBINS * 4; // 57344 B
    cudaFuncSetAttribute(select_kernel,
                         cudaFuncAttributeMaxDynamicSharedMemorySize, (int)smem);
    thresh_kernel<<<NB, TT>>>(logits);
    dim3 sg(NCH, NB, 1);
    stream_kernel<<<sg, ST>>>(logits);
    select_kernel<<<NB, ST, smem>>>(logits, boxes, (float*)d_out);
}

// round 8
// speedup vs baseline: 1.7559x; 1.1976x over previous
#include <cuda_runtime.h>
#include <math_constants.h>

#define NB 256
#define NQ 1000
#define NC 80
#define NN 80000          // NQ * NC per batch
#define TOPK 300
#define TT 1024           // thresh kernel threads
#define ST 256            // stream/select kernel threads
#define NCHS 10           // chunks per batch (stream)
#define SCHS 8192         // elements per chunk
#define CHCAP 1024        // per-chunk survivor slice capacity
#define SCAP 6144         // smem candidate buffer entries (u64)
#define LISTCAP 2048
#define HBINS 2048
#define TSAMP 64          // sample-rank target for streaming threshold
#define TSEL 384          // final selection rank (slack over 300)
#define REFINE_AT 448     // force sub-bin refine if would-be msel exceeds this

// ---------------- global scratch (static __device__, no allocs) ----------------
__device__ unsigned long long g_bufc[NB][NCHS][CHCAP];  // per-chunk survivor slices
__device__ int g_cntc[NB][NCHS];                        // per-chunk counts (plain stores)
__device__ float g_thrf[NB];

// ---------- monotone float<->uint mapping ----------
__device__ __forceinline__ unsigned flipf(unsigned b) {
    return (b & 0x80000000u) ? ~b : (b | 0x80000000u);
}
__device__ __forceinline__ unsigned unflipf(unsigned u) {
    return (u & 0x80000000u) ? (u & 0x7FFFFFFFu) : ~u;
}

// ---------- sigmoid matching XLA: logistic(x) = 0.5 + 0.5*tanh(0.5*x) ----------
__device__ __forceinline__ float sigmoid_ref(float x) {
    float hx = __fmul_rn(0.5f, x);
    float ax = fabsf(hx);
    float xc = fminf(fmaxf(hx, -9.0f), 9.0f);
    float x2 = __fmul_rn(xc, xc);
    float p = -2.76076847742355e-16f;
    p = fmaf(x2, p, 2.00018790482477e-13f);
    p = fmaf(x2, p, -8.60467152213735e-11f);
    p = fmaf(x2, p, 5.12229709037114e-08f);
    p = fmaf(x2, p, 1.48572235717979e-05f);
    p = fmaf(x2, p, 6.37261928875436e-04f);
    p = fmaf(x2, p, 4.89352455891786e-03f);
    p = __fmul_rn(xc, p);
    float q = 1.19825839466702e-06f;
    q = fmaf(x2, q, 1.18534705686654e-04f);
    q = fmaf(x2, q, 2.26843463243900e-03f);
    q = fmaf(x2, q, 4.89352518554385e-03f);
    float t = __fdiv_rn(p, q);
    t = (ax < 4e-4f) ? hx : t;
    return __fadd_rn(__fmul_rn(0.5f, t), 0.5f);
}

// ================= 1024-thread suffix scan (thresh kernel) =================
__device__ __forceinline__ void suffix_scan1024(unsigned* hist, unsigned* wsum) {
    const int tid = threadIdx.x;
    const int lane = tid & 31;
    const int w = tid >> 5;
    unsigned x0 = hist[2047 - 2 * tid];
    unsigned x1 = hist[2046 - 2 * tid];
    unsigned s = x0 + x1;
    unsigned incl = s;
    #pragma unroll
    for (int o = 1; o < 32; o <<= 1) {
        unsigned v = __shfl_up_sync(0xFFFFFFFFu, incl, o);
        if (lane >= o) incl += v;
    }
    if (lane == 31) wsum[w] = incl;
    unsigned excl_lane = incl - s;
    __syncthreads();
    if (tid < 32) {
        unsigned v = wsum[tid];
        unsigned wincl = v;
        #pragma unroll
        for (int o = 1; o < 32; o <<= 1) {
            unsigned t2 = __shfl_up_sync(0xFFFFFFFFu, wincl, o);
            if (tid >= o) wincl += t2;
        }
        wsum[tid] = wincl - v;
    }
    __syncthreads();
    unsigned excl = wsum[w] + excl_lane;
    hist[2047 - 2 * tid] = excl + x0;
    hist[2046 - 2 * tid] = excl + x0 + x1;
    __syncthreads();
}

// ================= 256-thread suffix scan over 2048 bins =================
__device__ __forceinline__ void suffix_scan256(unsigned* hist, unsigned* wsum8) {
    const int tid = threadIdx.x;
    const int lane = tid & 31;
    const int w = tid >> 5;
    const int base = HBINS - 8 - 8 * tid;
    unsigned x[8];
    #pragma unroll
    for (int j = 0; j < 8; ++j) x[j] = hist[base + j];
    unsigned tot = x[0] + x[1] + x[2] + x[3] + x[4] + x[5] + x[6] + x[7];
    unsigned incl = tot;
    #pragma unroll
    for (int o = 1; o < 32; o <<= 1) {
        unsigned t2 = __shfl_up_sync(0xFFFFFFFFu, incl, o);
        if (lane >= o) incl += t2;
    }
    if (lane == 31) wsum8[w] = incl;
    unsigned excl = incl - tot;
    __syncthreads();
    if (tid < 8) {
        unsigned v = wsum8[tid];
        unsigned wincl = v;
        #pragma unroll
        for (int o = 1; o < 8; o <<= 1) {
            unsigned t2 = __shfl_up_sync(0xFFu, wincl, o);
            if (tid >= o) wincl += t2;
        }
        wsum8[tid] = wincl - v;
    }
    __syncthreads();
    unsigned carry = wsum8[w] + excl;
    unsigned run = carry;
    #pragma unroll
    for (int j = 7; j >= 0; --j) { run += x[j]; hist[base + j] = run; }
    __syncthreads();
}

// ---------- smem append (fallback path only), 256-thread ----------
__device__ __forceinline__ void append_smem256(unsigned long long* buf, int* cnt,
                                               unsigned ub, unsigned idx) {
    unsigned long long key = ((unsigned long long)ub << 32) | idx;
    unsigned mask = __activemask();
    int lane = threadIdx.x & 31;
    int leader = __ffs(mask) - 1;
    int pos = 0;
    if (lane == leader) pos = atomicAdd(cnt, __popc(mask));
    pos = __shfl_sync(mask, pos, leader) + __popc(mask & ((1u << lane) - 1u));
    if (pos < SCAP) buf[pos] = key;
}

// ---------- 256-thread histogram radix-select ----------
// After suffix scan, hist[i] = count of keys with bin >= i.
// sc[0]=B, sc[1]=B2, sc[2]=refined, sc[3]=gathered, sc[4]=nAbove
__device__ void run_select256(unsigned long long* buf, unsigned long long* lst,
                              unsigned* hist, unsigned* wsum8, int* sc, int n, int target) {
    const int tid = threadIdx.x;
    if (n <= target) {
        if (tid == 0) { sc[0] = 0; sc[1] = 0; sc[2] = 0; sc[3] = n; }
        __syncthreads();
        for (int i = tid; i < n; i += ST) lst[i] = buf[i];
        __syncthreads();
        return;
    }
    for (int i = tid; i < HBINS; i += ST) hist[i] = 0;
    __syncthreads();
    for (int i = tid; i < n; i += ST)
        atomicAdd(&hist[(unsigned)(buf[i] >> 53)], 1u);
    __syncthreads();
    suffix_scan256(hist, wsum8);
    for (int i = tid * 8; i < tid * 8 + 8; ++i) {
        unsigned s = hist[i];
        unsigned sn = (i + 1 < HBINS) ? hist[i + 1] : 0u;
        if (s >= (unsigned)target && sn < (unsigned)target) { sc[0] = i; sc[4] = (int)sn; }
    }
    if (tid == 0) { sc[2] = 0; sc[3] = 0; }
    __syncthreads();
    const int B = sc[0];
    const int nAbove = sc[4];
    const int wouldSel = (int)hist[B];        // suffix(B) = would-be msel
    int refined = 0, B2 = 0;
    if (wouldSel > REFINE_AT) {               // refine boundary bin on next 11 bits
        __syncthreads();
        for (int i = tid; i < HBINS; i += ST) hist[i] = 0;
        __syncthreads();
        for (int i = tid; i < n; i += ST) {
            unsigned long long k = buf[i];
            if ((unsigned)(k >> 53) == (unsigned)B)
                atomicAdd(&hist[(unsigned)(k >> 42) & 0x7FFu], 1u);
        }
        __syncthreads();
        suffix_scan256(hist, wsum8);
        int extra = target - nAbove;
        for (int i = tid * 8; i < tid * 8 + 8; ++i) {
            unsigned s = hist[i];
            unsigned sn = (i + 1 < HBINS) ? hist[i + 1] : 0u;
            if (s >= (unsigned)extra && sn < (unsigned)extra) sc[1] = i;
        }
        if (tid == 0) sc[2] = 1;
        __syncthreads();
        refined = 1;
        B2 = sc[1];
    }
    for (int i = tid; i < n; i += ST) {
        unsigned long long k = buf[i];
        unsigned bin = (unsigned)(k >> 53);
        bool sel = (bin > (unsigned)B) ||
                   (bin == (unsigned)B &&
                    (!refined || (((unsigned)(k >> 42) & 0x7FFu) >= (unsigned)B2)));
        if (sel) {
            int p = atomicAdd(&sc[3], 1);
            if (p < LISTCAP) lst[p] = k;
        }
    }
    __syncthreads();
}

// ================= kernel A: per-batch threshold from 4096-sample =================
extern "C" __global__ void __launch_bounds__(TT)
thresh_kernel(const float* __restrict__ logits) {
    __shared__ unsigned hist[HBINS];
    __shared__ unsigned wsum[32];
    __shared__ int s_bin;
    const int tid = threadIdx.x;
    const int b = blockIdx.x;
    const float* Lp = logits + (size_t)b * NN;

    hist[tid] = 0; hist[tid + TT] = 0;
    if (tid == 0) s_bin = 0;
    __syncthreads();
    {
        float4 v = *reinterpret_cast<const float4*>(Lp + tid * 4);
        atomicAdd(&hist[flipf(__float_as_uint(v.x)) >> 21], 1u);
        atomicAdd(&hist[flipf(__float_as_uint(v.y)) >> 21], 1u);
        atomicAdd(&hist[flipf(__float_as_uint(v.z)) >> 21], 1u);
        atomicAdd(&hist[flipf(__float_as_uint(v.w)) >> 21], 1u);
    }
    __syncthreads();
    suffix_scan1024(hist, wsum);
    {
        unsigned s0 = hist[tid];
        unsigned s0n = (tid + 1 < HBINS) ? hist[tid + 1] : 0u;
        if (s0 >= TSAMP && s0n < TSAMP) s_bin = tid;
        unsigned s1 = hist[tid + TT];
        unsigned s1n = (tid + TT + 1 < HBINS) ? hist[tid + TT + 1] : 0u;
        if (s1 >= TSAMP && s1n < TSAMP) s_bin = tid + TT;
    }
    __syncthreads();
    if (tid == 0) {
        g_thrf[b] = (s_bin == 0) ? -CUDART_INF_F
                                 : __uint_as_float(unflipf((unsigned)s_bin << 21));
    }
}

// ================= kernel B: lean full-bandwidth filter stream =================
// ~0.25 inst/element hot path: 3 FMNMX + FSETP + VOTE per 4 elements; ballot/popc
// aggregated append only on warp-hit. 8 LDG.128 in flight per thread.
extern "C" __global__ void __launch_bounds__(ST, 4)
stream_kernel(const float* __restrict__ logits) {
    __shared__ unsigned long long skeys[CHCAP];
    __shared__ int s_cnt;

    const int tid = threadIdx.x;
    const int lane = tid & 31;
    const int chunk = blockIdx.x;          // 0..NCHS-1
    const int b = blockIdx.y;              // 0..NB-1
    const float* Lp = logits + (size_t)b * NN + chunk * SCHS;
    const int rem = NN - chunk * SCHS;
    const float thr = g_thrf[b];
    const unsigned ltmask = (1u << lane) - 1u;

    if (tid == 0) s_cnt = 0;
    __syncthreads();

    float4 v[8];
    bool ok[8];
    #pragma unroll
    for (int i = 0; i < 8; ++i) {          // 8 independent loads up front (MLP)
        int off = i * (ST * 4) + tid * 4;
        ok[i] = off < rem;
        if (ok[i]) v[i] = __ldcs(reinterpret_cast<const float4*>(Lp + off));
    }

    #pragma unroll
    for (int i = 0; i < 8; ++i) {
        float4 w = v[i];
        float gmax = ok[i] ? fmaxf(fmaxf(w.x, w.y), fmaxf(w.z, w.w)) : -CUDART_INF_F;
        if (__any_sync(0xFFFFFFFFu, gmax >= thr)) {   // rare-path aggregation
            int base = chunk * SCHS + i * (ST * 4) + tid * 4;
            bool c0 = ok[i] && (w.x >= thr);
            bool c1 = ok[i] && (w.y >= thr);
            bool c2 = ok[i] && (w.z >= thr);
            bool c3 = ok[i] && (w.w >= thr);
            unsigned m0 = __ballot_sync(0xFFFFFFFFu, c0);
            unsigned m1 = __ballot_sync(0xFFFFFFFFu, c1);
            unsigned m2 = __ballot_sync(0xFFFFFFFFu, c2);
            unsigned m3 = __ballot_sync(0xFFFFFFFFu, c3);
            int tot = __popc(m0) + __popc(m1) + __popc(m2) + __popc(m3);
            int wb = 0;
            if (lane == 0) wb = atomicAdd(&s_cnt, tot);
            wb = __shfl_sync(0xFFFFFFFFu, wb, 0);
            int p = wb;
            if (c0) {
                int ix = p + __popc(m0 & ltmask);
                if (ix < CHCAP) skeys[ix] = ((unsigned long long)flipf(__float_as_uint(w.x)) << 32) | (unsigned)base;
            }
            p += __popc(m0);
            if (c1) {
                int ix = p + __popc(m1 & ltmask);
                if (ix < CHCAP) skeys[ix] = ((unsigned long long)flipf(__float_as_uint(w.y)) << 32) | (unsigned)(base + 1);
            }
            p += __popc(m1);
            if (c2) {
                int ix = p + __popc(m2 & ltmask);
                if (ix < CHCAP) skeys[ix] = ((unsigned long long)flipf(__float_as_uint(w.z)) << 32) | (unsigned)(base + 2);
            }
            p += __popc(m2);
            if (c3) {
                int ix = p + __popc(m3 & ltmask);
                if (ix < CHCAP) skeys[ix] = ((unsigned long long)flipf(__float_as_uint(w.w)) << 32) | (unsigned)(base + 3);
            }
        }
    }
    __syncthreads();
    const int cn = s_cnt;
    for (int i = tid; i < min(cn, CHCAP); i += ST)
        g_bufc[b][chunk][i] = skeys[i];
    if (tid == 0) g_cntc[b][chunk] = cn;      // raw count (overflow detect)
}

// ================= kernel C: gather + select + sigmoid + rank + write =================
extern "C" __global__ void __launch_bounds__(ST)
select_kernel(const float* __restrict__ logits,
              const float* __restrict__ boxes,
              float* __restrict__ out) {
    extern __shared__ unsigned char smem_raw[];
    unsigned long long* buf = reinterpret_cast<unsigned long long*>(smem_raw); // SCAP
    unsigned long long* lst = buf + SCAP;                                      // LISTCAP
    unsigned* hist = reinterpret_cast<unsigned*>(lst + LISTCAP);               // HBINS
    __shared__ unsigned wsum8[8];
    __shared__ int s_cnt;
    __shared__ int sc[5];
    __shared__ int s_off[NCHS + 1];
    __shared__ int s_bad;

    const int tid = threadIdx.x;
    const int b = blockIdx.x;

    if (tid < NCHS) s_off[tid] = g_cntc[b][tid];
    __syncthreads();
    if (tid == 0) {
        int acc = 0, bd = 0;
        for (int s2 = 0; s2 < NCHS; ++s2) {
            int c = s_off[s2];
            if (c > CHCAP) { bd = 1; c = CHCAP; }
            s_off[s2] = acc;
            acc += c;
        }
        s_off[NCHS] = acc;
        s_bad = bd || (acc > SCAP) || (acc < TOPK);
    }
    __syncthreads();
    int m = s_off[NCHS];

    if (!s_bad) {
        for (int s2 = 0; s2 < NCHS; ++s2) {
            int o0 = s_off[s2];
            int len = s_off[s2 + 1] - o0;
            for (int i = tid; i < len; i += ST)
                buf[o0 + i] = g_bufc[b][s2][i];
        }
        __syncthreads();
    } else {
        // ---- fallback: adaptive restream of whole batch (never taken normally) ----
        if (tid == 0) s_cnt = 0;
        __syncthreads();
        unsigned thr2 = 0u;
        const float* Lb = logits + (size_t)b * NN;
        const int ngr = (NN + ST * 4 - 1) / (ST * 4);
        for (int g = 0; g < ngr; ++g) {
            int base = g * (ST * 4) + tid * 4;
            if (base < NN) {
                float4 w = *reinterpret_cast<const float4*>(Lb + base);
                unsigned ub[4] = {flipf(__float_as_uint(w.x)), flipf(__float_as_uint(w.y)),
                                  flipf(__float_as_uint(w.z)), flipf(__float_as_uint(w.w))};
                #pragma unroll
                for (int e = 0; e < 4; ++e)
                    if (ub[e] >= thr2) append_smem256(buf, &s_cnt, ub[e], base + e);
            }
            __syncthreads();
            if (s_cnt > SCAP - ST * 4) {
                run_select256(buf, lst, hist, wsum8, sc, min(s_cnt, SCAP), TSEL);
                int mm = min(sc[3], LISTCAP);
                for (int i = tid; i < mm; i += ST) buf[i] = lst[i];
                __syncthreads();
                if (tid == 0) s_cnt = mm;
                __syncthreads();
                thr2 = sc[2] ? (((unsigned)sc[0] << 21) | ((unsigned)sc[1] << 10))
                             : ((unsigned)sc[0] << 21);
            }
        }
        m = min(s_cnt, SCAP);
    }

    // prune to ~TSEL best (forced sub-bin refine keeps msel ~= TSEL)
    run_select256(buf, lst, hist, wsum8, sc, m, TSEL);
    int msel = min(sc[3], LISTCAP);

    // sigmoid rank keys: score desc, index asc
    for (int i = tid; i < msel; i += ST) {
        unsigned long long k = lst[i];
        unsigned u = (unsigned)(k >> 32);
        unsigned idx = (unsigned)k;
        float s = sigmoid_ref(__uint_as_float(unflipf(u)));
        lst[i] = ((unsigned long long)__float_as_uint(s) << 32) |
                 (unsigned)(0xFFFFFFFFu - idx);
    }
    __syncthreads();

    // exact rank by counting (keys unique via idx bits); write outputs for rank < TOPK
    for (int i = tid; i < msel; i += ST) {
        unsigned long long k = lst[i];
        int r = 0;
        for (int j = 0; j < msel; ++j) r += (lst[j] > k) ? 1 : 0;
        if (r < TOPK) {
            unsigned idx = 0xFFFFFFFFu - (unsigned)k;
            float s = __uint_as_float((unsigned)(k >> 32));
            int q = (int)(idx / NC);
            int c = (int)(idx - (unsigned)q * NC);
            size_t o = (size_t)b * TOPK + (size_t)r;
            out[o] = (float)c;                                   // labels
            float4 bx = *reinterpret_cast<const float4*>(
                boxes + ((size_t)b * NQ + (size_t)q) * 4);
            float4 xy;
            xy.x = bx.x - 0.5f * bx.z;
            xy.y = bx.y - 0.5f * bx.w;
            xy.z = bx.x + 0.5f * bx.z;
            xy.w = bx.y + 0.5f * bx.w;
            *reinterpret_cast<float4*>(out + (size_t)NB * TOPK + o * 4) = xy;  // boxes
            out[(size_t)NB * TOPK * 5 + o] = s;                  // scores
        }
    }
}

extern "C" void kernel_launch(void* const* d_in, const int* in_sizes, int n_in,
                              void* d_out, int out_size) {
    const float* logits = (const float*)d_in[0];
    const float* boxes = (const float*)d_in[1];
    size_t smem = (size_t)SCAP * 8 + (size_t)LISTCAP * 8 + (size_t)HBINS * 4; // 73728 B
    cudaFuncSetAttribute(select_kernel,
                         cudaFuncAttributeMaxDynamicSharedMemorySize, (int)smem);
    thresh_kernel<<<NB, TT>>>(logits);
    dim3 sg(NCHS, NB, 1);
    stream_kernel<<<sg, ST>>>(logits);
    select_kernel<<<NB, ST, smem>>>(logits, boxes, (float*)d_out);
}

// round 9
// speedup vs baseline: 2.0272x; 1.1545x over previous
#include <cuda_runtime.h>
#include <math_constants.h>

#define NB 256
#define NQ 1000
#define NC 80
#define NN 80000          // NQ * NC per batch
#define TOPK 300
#define NT 1024           // select kernel threads
#define ST 256            // stream kernel threads
#define NCHS 10           // chunks per batch (stream)
#define SCHS 8192         // elements per chunk
#define CHCAP 1024        // per-chunk survivor slice capacity
#define SCAP 6144         // smem candidate buffer entries (u64)
#define LISTCAP 2048
#define HBINS 2048
#define TSEL 384          // final selection rank (slack over 300)
#define REFINE_AT 448     // force sub-bin refine if would-be msel exceeds this
#define THRF 1.84f        // fixed stream threshold (~2600 survivors/batch on N(0,1));
                          // ANY data that breaks this triggers the exact fallback path

// ---------------- global scratch (static __device__, no allocs) ----------------
__device__ unsigned long long g_bufc[NB][NCHS][CHCAP];  // per-chunk survivor slices
__device__ int g_cntc[NB][NCHS];                        // per-chunk counts (plain stores)

// ---------- monotone float<->uint mapping ----------
__device__ __forceinline__ unsigned flipf(unsigned b) {
    return (b & 0x80000000u) ? ~b : (b | 0x80000000u);
}
__device__ __forceinline__ unsigned unflipf(unsigned u) {
    return (u & 0x80000000u) ? (u & 0x7FFFFFFFu) : ~u;
}

// ---------- sigmoid matching XLA: logistic(x) = 0.5 + 0.5*tanh(0.5*x) ----------
__device__ __forceinline__ float sigmoid_ref(float x) {
    float hx = __fmul_rn(0.5f, x);
    float ax = fabsf(hx);
    float xc = fminf(fmaxf(hx, -9.0f), 9.0f);
    float x2 = __fmul_rn(xc, xc);
    float p = -2.76076847742355e-16f;
    p = fmaf(x2, p, 2.00018790482477e-13f);
    p = fmaf(x2, p, -8.60467152213735e-11f);
    p = fmaf(x2, p, 5.12229709037114e-08f);
    p = fmaf(x2, p, 1.48572235717979e-05f);
    p = fmaf(x2, p, 6.37261928875436e-04f);
    p = fmaf(x2, p, 4.89352455891786e-03f);
    p = __fmul_rn(xc, p);
    float q = 1.19825839466702e-06f;
    q = fmaf(x2, q, 1.18534705686654e-04f);
    q = fmaf(x2, q, 2.26843463243900e-03f);
    q = fmaf(x2, q, 4.89352518554385e-03f);
    float t = __fdiv_rn(p, q);
    t = (ax < 4e-4f) ? hx : t;
    return __fadd_rn(__fmul_rn(0.5f, t), 0.5f);
}

// ================= 1024-thread suffix scan over 2048 bins =================
__device__ __forceinline__ void suffix_scan1024(unsigned* hist, unsigned* wsum) {
    const int tid = threadIdx.x;
    const int lane = tid & 31;
    const int w = tid >> 5;
    unsigned x0 = hist[2047 - 2 * tid];
    unsigned x1 = hist[2046 - 2 * tid];
    unsigned s = x0 + x1;
    unsigned incl = s;
    #pragma unroll
    for (int o = 1; o < 32; o <<= 1) {
        unsigned v = __shfl_up_sync(0xFFFFFFFFu, incl, o);
        if (lane >= o) incl += v;
    }
    if (lane == 31) wsum[w] = incl;
    unsigned excl_lane = incl - s;
    __syncthreads();
    if (tid < 32) {
        unsigned v = wsum[tid];
        unsigned wincl = v;
        #pragma unroll
        for (int o = 1; o < 32; o <<= 1) {
            unsigned t2 = __shfl_up_sync(0xFFFFFFFFu, wincl, o);
            if (tid >= o) wincl += t2;
        }
        wsum[tid] = wincl - v;
    }
    __syncthreads();
    unsigned excl = wsum[w] + excl_lane;
    hist[2047 - 2 * tid] = excl + x0;
    hist[2046 - 2 * tid] = excl + x0 + x1;
    __syncthreads();
}

// ---------- smem append (fallback path only) ----------
__device__ __forceinline__ void append_smem(unsigned long long* buf, int* cnt,
                                            unsigned ub, unsigned idx) {
    unsigned long long key = ((unsigned long long)ub << 32) | idx;
    unsigned mask = __activemask();
    int lane = threadIdx.x & 31;
    int leader = __ffs(mask) - 1;
    int pos = 0;
    if (lane == leader) pos = atomicAdd(cnt, __popc(mask));
    pos = __shfl_sync(mask, pos, leader) + __popc(mask & ((1u << lane) - 1u));
    if (pos < SCAP) buf[pos] = key;
}

// ---------- 1024-thread histogram radix-select ----------
// After suffix scan, hist[i] = count of keys with bin >= i.
// sc[0]=B, sc[1]=B2, sc[2]=refined, sc[3]=gathered, sc[4]=nAbove
__device__ void run_select(unsigned long long* buf, unsigned long long* lst,
                           unsigned* hist, unsigned* wsum, int* sc, int n, int target) {
    const int tid = threadIdx.x;
    if (n <= target) {
        if (tid == 0) { sc[0] = 0; sc[1] = 0; sc[2] = 0; sc[3] = n; }
        __syncthreads();
        for (int i = tid; i < n; i += NT) lst[i] = buf[i];
        __syncthreads();
        return;
    }
    hist[tid] = 0; hist[tid + NT] = 0;
    __syncthreads();
    for (int i = tid; i < n; i += NT)
        atomicAdd(&hist[(unsigned)(buf[i] >> 53)], 1u);
    __syncthreads();
    suffix_scan1024(hist, wsum);
    {
        unsigned s0 = hist[tid];
        unsigned s0n = (tid + 1 < HBINS) ? hist[tid + 1] : 0u;
        if (s0 >= (unsigned)target && s0n < (unsigned)target) { sc[0] = tid; sc[4] = (int)s0n; }
        unsigned s1 = hist[tid + NT];
        unsigned s1n = (tid + NT + 1 < HBINS) ? hist[tid + NT + 1] : 0u;
        if (s1 >= (unsigned)target && s1n < (unsigned)target) { sc[0] = tid + NT; sc[4] = (int)s1n; }
    }
    if (tid == 0) { sc[2] = 0; sc[3] = 0; }
    __syncthreads();
    const int B = sc[0];
    const int nAbove = sc[4];
    const int wouldSel = (int)hist[B];        // suffix(B) = would-be msel
    int refined = 0, B2 = 0;
    if (wouldSel > REFINE_AT) {               // refine boundary bin on next 11 bits
        __syncthreads();
        hist[tid] = 0; hist[tid + NT] = 0;
        __syncthreads();
        for (int i = tid; i < n; i += NT) {
            unsigned long long k = buf[i];
            if ((unsigned)(k >> 53) == (unsigned)B)
                atomicAdd(&hist[(unsigned)(k >> 42) & 0x7FFu], 1u);
        }
        __syncthreads();
        suffix_scan1024(hist, wsum);
        int extra = target - nAbove;
        {
            unsigned s0 = hist[tid];
            unsigned s0n = (tid + 1 < HBINS) ? hist[tid + 1] : 0u;
            if (s0 >= (unsigned)extra && s0n < (unsigned)extra) sc[1] = tid;
            unsigned s1 = hist[tid + NT];
            unsigned s1n = (tid + NT + 1 < HBINS) ? hist[tid + NT + 1] : 0u;
            if (s1 >= (unsigned)extra && s1n < (unsigned)extra) sc[1] = tid + NT;
        }
        if (tid == 0) sc[2] = 1;
        __syncthreads();
        refined = 1;
        B2 = sc[1];
    }
    for (int i = tid; i < n; i += NT) {
        unsigned long long k = buf[i];
        unsigned bin = (unsigned)(k >> 53);
        bool sel = (bin > (unsigned)B) ||
                   (bin == (unsigned)B &&
                    (!refined || (((unsigned)(k >> 42) & 0x7FFu) >= (unsigned)B2)));
        if (sel) {
            int p = atomicAdd(&sc[3], 1);
            if (p < LISTCAP) lst[p] = k;
        }
    }
    __syncthreads();
}

// ================= kernel B: lean full-bandwidth filter stream =================
// No threshold dependency at head: loads issue immediately. Fixed THRF compare,
// ballot-aggregated append only on warp-hit, 8 LDG.128 in flight per thread.
extern "C" __global__ void __launch_bounds__(ST, 4)
stream_kernel(const float* __restrict__ logits) {
    __shared__ unsigned long long skeys[CHCAP];
    __shared__ int s_cnt;

    const int tid = threadIdx.x;
    const int lane = tid & 31;
    const int chunk = blockIdx.x;          // 0..NCHS-1
    const int b = blockIdx.y;              // 0..NB-1
    const float* Lp = logits + (size_t)b * NN + chunk * SCHS;
    const int rem = NN - chunk * SCHS;
    const unsigned ltmask = (1u << lane) - 1u;

    if (tid == 0) s_cnt = 0;
    __syncthreads();

    float4 v[8];
    bool ok[8];
    #pragma unroll
    for (int i = 0; i < 8; ++i) {          // 8 independent loads up front (MLP)
        int off = i * (ST * 4) + tid * 4;
        ok[i] = off < rem;
        if (ok[i]) v[i] = __ldcs(reinterpret_cast<const float4*>(Lp + off));
    }

    #pragma unroll
    for (int i = 0; i < 8; ++i) {
        float4 w = v[i];
        float gmax = ok[i] ? fmaxf(fmaxf(w.x, w.y), fmaxf(w.z, w.w)) : -CUDART_INF_F;
        if (__any_sync(0xFFFFFFFFu, gmax >= THRF)) {
            int base = chunk * SCHS + i * (ST * 4) + tid * 4;
            bool c0 = ok[i] && (w.x >= THRF);
            bool c1 = ok[i] && (w.y >= THRF);
            bool c2 = ok[i] && (w.z >= THRF);
            bool c3 = ok[i] && (w.w >= THRF);
            unsigned m0 = __ballot_sync(0xFFFFFFFFu, c0);
            unsigned m1 = __ballot_sync(0xFFFFFFFFu, c1);
            unsigned m2 = __ballot_sync(0xFFFFFFFFu, c2);
            unsigned m3 = __ballot_sync(0xFFFFFFFFu, c3);
            int tot = __popc(m0) + __popc(m1) + __popc(m2) + __popc(m3);
            int wb = 0;
            if (lane == 0) wb = atomicAdd(&s_cnt, tot);
            wb = __shfl_sync(0xFFFFFFFFu, wb, 0);
            int p = wb;
            if (c0) {
                int ix = p + __popc(m0 & ltmask);
                if (ix < CHCAP) skeys[ix] = ((unsigned long long)flipf(__float_as_uint(w.x)) << 32) | (unsigned)base;
            }
            p += __popc(m0);
            if (c1) {
                int ix = p + __popc(m1 & ltmask);
                if (ix < CHCAP) skeys[ix] = ((unsigned long long)flipf(__float_as_uint(w.y)) << 32) | (unsigned)(base + 1);
            }
            p += __popc(m1);
            if (c2) {
                int ix = p + __popc(m2 & ltmask);
                if (ix < CHCAP) skeys[ix] = ((unsigned long long)flipf(__float_as_uint(w.z)) << 32) | (unsigned)(base + 2);
            }
            p += __popc(m2);
            if (c3) {
                int ix = p + __popc(m3 & ltmask);
                if (ix < CHCAP) skeys[ix] = ((unsigned long long)flipf(__float_as_uint(w.w)) << 32) | (unsigned)(base + 3);
            }
        }
    }
    __syncthreads();
    const int cn = s_cnt;
    for (int i = tid; i < min(cn, CHCAP); i += ST)
        g_bufc[b][chunk][i] = skeys[i];
    if (tid == 0) g_cntc[b][chunk] = cn;      // raw count (overflow detect)
}

// ================= kernel C: gather + select + sigmoid + rank + write =================
extern "C" __global__ void __launch_bounds__(NT)
select_kernel(const float* __restrict__ logits,
              const float* __restrict__ boxes,
              float* __restrict__ out) {
    extern __shared__ unsigned char smem_raw[];
    unsigned long long* buf = reinterpret_cast<unsigned long long*>(smem_raw); // SCAP
    unsigned long long* lst = buf + SCAP;                                      // LISTCAP
    unsigned* hist = reinterpret_cast<unsigned*>(lst + LISTCAP);               // HBINS
    __shared__ unsigned wsum[32];
    __shared__ int s_cnt;
    __shared__ int sc[5];
    __shared__ int s_off[NCHS + 1];
    __shared__ int s_bad;

    const int tid = threadIdx.x;
    const int lane = tid & 31;
    const int wid = tid >> 5;                 // 32 warps
    const int b = blockIdx.x;

    if (tid < NCHS) s_off[tid] = g_cntc[b][tid];
    __syncthreads();
    if (tid == 0) {
        int acc = 0, bd = 0;
        for (int s2 = 0; s2 < NCHS; ++s2) {
            int c = s_off[s2];
            if (c > CHCAP) { bd = 1; c = CHCAP; }
            s_off[s2] = acc;
            acc += c;
        }
        s_off[NCHS] = acc;
        s_bad = bd || (acc > SCAP) || (acc < TOPK);
    }
    __syncthreads();
    int m = s_off[NCHS];

    if (!s_bad) {
        // parallel gather: warps spread across slices -> one latency burst
        for (int s2 = wid; s2 < NCHS * 4; s2 += 32) {          // 4 warps per slice
            int sl = s2 % NCHS;
            int part = s2 / NCHS;                               // 0..3
            int o0 = s_off[sl];
            int len = s_off[sl + 1] - o0;
            for (int i = part * 32 + lane; i < len; i += 128)
                buf[o0 + i] = g_bufc[b][sl][i];
        }
        __syncthreads();
    } else {
        // ---- fallback: adaptive restream of whole batch (never taken normally) ----
        if (tid == 0) s_cnt = 0;
        __syncthreads();
        unsigned thr2 = 0u;
        const float* Lb = logits + (size_t)b * NN;
        const int ngr = (NN + NT * 4 - 1) / (NT * 4);
        for (int g = 0; g < ngr; ++g) {
            int base = g * (NT * 4) + tid * 4;
            if (base < NN) {
                float4 w = *reinterpret_cast<const float4*>(Lb + base);
                unsigned ub[4] = {flipf(__float_as_uint(w.x)), flipf(__float_as_uint(w.y)),
                                  flipf(__float_as_uint(w.z)), flipf(__float_as_uint(w.w))};
                #pragma unroll
                for (int e = 0; e < 4; ++e)
                    if (ub[e] >= thr2) append_smem(buf, &s_cnt, ub[e], base + e);
            }
            __syncthreads();
            if (s_cnt > SCAP - NT * 4) {
                run_select(buf, lst, hist, wsum, sc, min(s_cnt, SCAP), TSEL);
                int mm = min(sc[3], LISTCAP);
                for (int i = tid; i < mm; i += NT) buf[i] = lst[i];
                __syncthreads();
                if (tid == 0) s_cnt = mm;
                __syncthreads();
                thr2 = sc[2] ? (((unsigned)sc[0] << 21) | ((unsigned)sc[1] << 10))
                             : ((unsigned)sc[0] << 21);
            }
        }
        m = min(s_cnt, SCAP);
    }

    // prune to ~TSEL best (forced sub-bin refine keeps msel ~= TSEL)
    run_select(buf, lst, hist, wsum, sc, m, TSEL);
    int msel = min(sc[3], LISTCAP);

    // sigmoid rank keys: score desc, index asc
    for (int i = tid; i < msel; i += NT) {
        unsigned long long k = lst[i];
        unsigned u = (unsigned)(k >> 32);
        unsigned idx = (unsigned)k;
        float s = sigmoid_ref(__uint_as_float(unflipf(u)));
        lst[i] = ((unsigned long long)__float_as_uint(s) << 32) |
                 (unsigned)(0xFFFFFFFFu - idx);
    }
    __syncthreads();

    // exact rank by counting (keys unique via idx bits); write outputs for rank < TOPK
    for (int i = tid; i < msel; i += NT) {
        unsigned long long k = lst[i];
        int r = 0;
        for (int j = 0; j < msel; ++j) r += (lst[j] > k) ? 1 : 0;
        if (r < TOPK) {
            unsigned idx = 0xFFFFFFFFu - (unsigned)k;
            float s = __uint_as_float((unsigned)(k >> 32));
            int q = (int)(idx / NC);
            int c = (int)(idx - (unsigned)q * NC);
            size_t o = (size_t)b * TOPK + (size_t)r;
            out[o] = (float)c;                                   // labels
            float4 bx = *reinterpret_cast<const float4*>(
                boxes + ((size_t)b * NQ + (size_t)q) * 4);
            float4 xy;
            xy.x = bx.x - 0.5f * bx.z;
            xy.y = bx.y - 0.5f * bx.w;
            xy.z = bx.x + 0.5f * bx.z;
            xy.w = bx.y + 0.5f * bx.w;
            *reinterpret_cast<float4*>(out + (size_t)NB * TOPK + o * 4) = xy;  // boxes
            out[(size_t)NB * TOPK * 5 + o] = s;                  // scores
        }
    }
}

extern "C" void kernel_launch(void* const* d_in, const int* in_sizes, int n_in,
                              void* d_out, int out_size) {
    const float* logits = (const float*)d_in[0];
    const float* boxes = (const float*)d_in[1];
    size_t smem = (size_t)SCAP * 8 + (size_t)LISTCAP * 8 + (size_t)HBINS * 4; // 73728 B
    cudaFuncSetAttribute(select_kernel,
                         cudaFuncAttributeMaxDynamicSharedMemorySize, (int)smem);
    dim3 sg(NCHS, NB, 1);
    stream_kernel<<<sg, ST>>>(logits);
    select_kernel<<<NB, NT, smem>>>(logits, boxes, (float*)d_out);
}

// round 10
// speedup vs baseline: 2.0377x; 1.0052x over previous
#include <cuda_runtime.h>
#include <math_constants.h>

#define NB 256
#define NQ 1000
#define NC 80
#define NN 80000          // NQ * NC per batch
#define TOPK 300
#define NT 1024           // select kernel threads
#define ST 256            // stream kernel threads
#define NCHS 5            // chunks per batch (stream)
#define SCHS 16384        // elements per chunk (2 rounds of 8 float4/thread)
#define CHCAP 1024        // per-chunk survivor slice capacity
#define SCAP 6144         // smem candidate buffer entries (u64)
#define LISTCAP 2048
#define HBINS 2048
#define TSEL 384          // final selection rank (slack over 300)
#define REFINE_AT 448     // force sub-bin refine if would-be msel exceeds this
#define SORTN 512         // bitonic sort size (power of two, >= typical msel)
#define THRF 1.84f        // fixed stream threshold (~2600 survivors/batch on N(0,1));
                          // ANY data that breaks this triggers the exact fallback path

// ---------------- global scratch (static __device__, no allocs) ----------------
__device__ unsigned long long g_bufc[NB][NCHS][CHCAP];  // per-chunk survivor slices
__device__ int g_cntc[NB][NCHS];                        // per-chunk counts (plain stores)

// ---------- monotone float<->uint mapping ----------
__device__ __forceinline__ unsigned flipf(unsigned b) {
    return (b & 0x80000000u) ? ~b : (b | 0x80000000u);
}
__device__ __forceinline__ unsigned unflipf(unsigned u) {
    return (u & 0x80000000u) ? (u & 0x7FFFFFFFu) : ~u;
}

// ---------- sigmoid matching XLA: logistic(x) = 0.5 + 0.5*tanh(0.5*x) ----------
__device__ __forceinline__ float sigmoid_ref(float x) {
    float hx = __fmul_rn(0.5f, x);
    float ax = fabsf(hx);
    float xc = fminf(fmaxf(hx, -9.0f), 9.0f);
    float x2 = __fmul_rn(xc, xc);
    float p = -2.76076847742355e-16f;
    p = fmaf(x2, p, 2.00018790482477e-13f);
    p = fmaf(x2, p, -8.60467152213735e-11f);
    p = fmaf(x2, p, 5.12229709037114e-08f);
    p = fmaf(x2, p, 1.48572235717979e-05f);
    p = fmaf(x2, p, 6.37261928875436e-04f);
    p = fmaf(x2, p, 4.89352455891786e-03f);
    p = __fmul_rn(xc, p);
    float q = 1.19825839466702e-06f;
    q = fmaf(x2, q, 1.18534705686654e-04f);
    q = fmaf(x2, q, 2.26843463243900e-03f);
    q = fmaf(x2, q, 4.89352518554385e-03f);
    float t = __fdiv_rn(p, q);
    t = (ax < 4e-4f) ? hx : t;
    return __fadd_rn(__fmul_rn(0.5f, t), 0.5f);
}

// ================= 1024-thread suffix scan over 2048 bins =================
__device__ __forceinline__ void suffix_scan1024(unsigned* hist, unsigned* wsum) {
    const int tid = threadIdx.x;
    const int lane = tid & 31;
    const int w = tid >> 5;
    unsigned x0 = hist[2047 - 2 * tid];
    unsigned x1 = hist[2046 - 2 * tid];
    unsigned s = x0 + x1;
    unsigned incl = s;
    #pragma unroll
    for (int o = 1; o < 32; o <<= 1) {
        unsigned v = __shfl_up_sync(0xFFFFFFFFu, incl, o);
        if (lane >= o) incl += v;
    }
    if (lane == 31) wsum[w] = incl;
    unsigned excl_lane = incl - s;
    __syncthreads();
    if (tid < 32) {
        unsigned v = wsum[tid];
        unsigned wincl = v;
        #pragma unroll
        for (int o = 1; o < 32; o <<= 1) {
            unsigned t2 = __shfl_up_sync(0xFFFFFFFFu, wincl, o);
            if (tid >= o) wincl += t2;
        }
        wsum[tid] = wincl - v;
    }
    __syncthreads();
    unsigned excl = wsum[w] + excl_lane;
    hist[2047 - 2 * tid] = excl + x0;
    hist[2046 - 2 * tid] = excl + x0 + x1;
    __syncthreads();
}

// ---------- smem append (fallback path only) ----------
__device__ __forceinline__ void append_smem(unsigned long long* buf, int* cnt,
                                            unsigned ub, unsigned idx) {
    unsigned long long key = ((unsigned long long)ub << 32) | idx;
    unsigned mask = __activemask();
    int lane = threadIdx.x & 31;
    int leader = __ffs(mask) - 1;
    int pos = 0;
    if (lane == leader) pos = atomicAdd(cnt, __popc(mask));
    pos = __shfl_sync(mask, pos, leader) + __popc(mask & ((1u << lane) - 1u));
    if (pos < SCAP) buf[pos] = key;
}

// ---------- 1024-thread histogram radix-select ----------
// After suffix scan, hist[i] = count of keys with bin >= i.
// sc[0]=B, sc[1]=B2, sc[2]=refined, sc[3]=gathered, sc[4]=nAbove
__device__ void run_select(unsigned long long* buf, unsigned long long* lst,
                           unsigned* hist, unsigned* wsum, int* sc, int n, int target) {
    const int tid = threadIdx.x;
    if (n <= target) {
        if (tid == 0) { sc[0] = 0; sc[1] = 0; sc[2] = 0; sc[3] = n; }
        __syncthreads();
        for (int i = tid; i < n; i += NT) lst[i] = buf[i];
        __syncthreads();
        return;
    }
    hist[tid] = 0; hist[tid + NT] = 0;
    __syncthreads();
    for (int i = tid; i < n; i += NT)
        atomicAdd(&hist[(unsigned)(buf[i] >> 53)], 1u);
    __syncthreads();
    suffix_scan1024(hist, wsum);
    {
        unsigned s0 = hist[tid];
        unsigned s0n = (tid + 1 < HBINS) ? hist[tid + 1] : 0u;
        if (s0 >= (unsigned)target && s0n < (unsigned)target) { sc[0] = tid; sc[4] = (int)s0n; }
        unsigned s1 = hist[tid + NT];
        unsigned s1n = (tid + NT + 1 < HBINS) ? hist[tid + NT + 1] : 0u;
        if (s1 >= (unsigned)target && s1n < (unsigned)target) { sc[0] = tid + NT; sc[4] = (int)s1n; }
    }
    if (tid == 0) { sc[2] = 0; sc[3] = 0; }
    __syncthreads();
    const int B = sc[0];
    const int nAbove = sc[4];
    const int wouldSel = (int)hist[B];        // suffix(B) = would-be msel
    int refined = 0, B2 = 0;
    if (wouldSel > REFINE_AT) {               // refine boundary bin on next 11 bits
        __syncthreads();
        hist[tid] = 0; hist[tid + NT] = 0;
        __syncthreads();
        for (int i = tid; i < n; i += NT) {
            unsigned long long k = buf[i];
            if ((unsigned)(k >> 53) == (unsigned)B)
                atomicAdd(&hist[(unsigned)(k >> 42) & 0x7FFu], 1u);
        }
        __syncthreads();
        suffix_scan1024(hist, wsum);
        int extra = target - nAbove;
        {
            unsigned s0 = hist[tid];
            unsigned s0n = (tid + 1 < HBINS) ? hist[tid + 1] : 0u;
            if (s0 >= (unsigned)extra && s0n < (unsigned)extra) sc[1] = tid;
            unsigned s1 = hist[tid + NT];
            unsigned s1n = (tid + NT + 1 < HBINS) ? hist[tid + NT + 1] : 0u;
            if (s1 >= (unsigned)extra && s1n < (unsigned)extra) sc[1] = tid + NT;
        }
        if (tid == 0) sc[2] = 1;
        __syncthreads();
        refined = 1;
        B2 = sc[1];
    }
    for (int i = tid; i < n; i += NT) {
        unsigned long long k = buf[i];
        unsigned bin = (unsigned)(k >> 53);
        bool sel = (bin > (unsigned)B) ||
                   (bin == (unsigned)B &&
                    (!refined || (((unsigned)(k >> 42) & 0x7FFu) >= (unsigned)B2)));
        if (sel) {
            int p = atomicAdd(&sc[3], 1);
            if (p < LISTCAP) lst[p] = k;
        }
    }
    __syncthreads();
}

// ================= kernel B: lean full-bandwidth filter stream =================
extern "C" __global__ void __launch_bounds__(ST, 4)
stream_kernel(const float* __restrict__ logits) {
    __shared__ unsigned long long skeys[CHCAP];
    __shared__ int s_cnt;

    const int tid = threadIdx.x;
    const int lane = tid & 31;
    const int chunk = blockIdx.x;          // 0..NCHS-1
    const int b = blockIdx.y;              // 0..NB-1
    const float* Lp = logits + (size_t)b * NN + chunk * SCHS;
    const int rem = NN - chunk * SCHS;
    const unsigned ltmask = (1u << lane) - 1u;

    if (tid == 0) s_cnt = 0;
    __syncthreads();

    #pragma unroll
    for (int rd = 0; rd < 2; ++rd) {       // 2 rounds x 8 in-flight LDG.128
        const int robase = rd * (ST * 4 * 8);
        float4 v[8];
        bool ok[8];
        #pragma unroll
        for (int i = 0; i < 8; ++i) {
            int off = robase + i * (ST * 4) + tid * 4;
            ok[i] = off < rem;
            if (ok[i]) v[i] = __ldcs(reinterpret_cast<const float4*>(Lp + off));
        }
        #pragma unroll
        for (int i = 0; i < 8; ++i) {
            float4 w = v[i];
            float gmax = ok[i] ? fmaxf(fmaxf(w.x, w.y), fmaxf(w.z, w.w)) : -CUDART_INF_F;
            if (__any_sync(0xFFFFFFFFu, gmax >= THRF)) {
                int base = chunk * SCHS + robase + i * (ST * 4) + tid * 4;
                bool c0 = ok[i] && (w.x >= THRF);
                bool c1 = ok[i] && (w.y >= THRF);
                bool c2 = ok[i] && (w.z >= THRF);
                bool c3 = ok[i] && (w.w >= THRF);
                unsigned m0 = __ballot_sync(0xFFFFFFFFu, c0);
                unsigned m1 = __ballot_sync(0xFFFFFFFFu, c1);
                unsigned m2 = __ballot_sync(0xFFFFFFFFu, c2);
                unsigned m3 = __ballot_sync(0xFFFFFFFFu, c3);
                int tot = __popc(m0) + __popc(m1) + __popc(m2) + __popc(m3);
                int wb = 0;
                if (lane == 0) wb = atomicAdd(&s_cnt, tot);
                wb = __shfl_sync(0xFFFFFFFFu, wb, 0);
                int p = wb;
                if (c0) {
                    int ix = p + __popc(m0 & ltmask);
                    if (ix < CHCAP) skeys[ix] = ((unsigned long long)flipf(__float_as_uint(w.x)) << 32) | (unsigned)base;
                }
                p += __popc(m0);
                if (c1) {
                    int ix = p + __popc(m1 & ltmask);
                    if (ix < CHCAP) skeys[ix] = ((unsigned long long)flipf(__float_as_uint(w.y)) << 32) | (unsigned)(base + 1);
                }
                p += __popc(m1);
                if (c2) {
                    int ix = p + __popc(m2 & ltmask);
                    if (ix < CHCAP) skeys[ix] = ((unsigned long long)flipf(__float_as_uint(w.z)) << 32) | (unsigned)(base + 2);
                }
                p += __popc(m2);
                if (c3) {
                    int ix = p + __popc(m3 & ltmask);
                    if (ix < CHCAP) skeys[ix] = ((unsigned long long)flipf(__float_as_uint(w.w)) << 32) | (unsigned)(base + 3);
                }
            }
        }
    }
    __syncthreads();
    const int cn = s_cnt;
    for (int i = tid; i < min(cn, CHCAP); i += ST)
        g_bufc[b][chunk][i] = skeys[i];
    if (tid == 0) g_cntc[b][chunk] = cn;      // raw count (overflow detect)
}

// ================= kernel C: gather + select + sigmoid + sort + write =================
extern "C" __global__ void __launch_bounds__(NT)
select_kernel(const float* __restrict__ logits,
              const float* __restrict__ boxes,
              float* __restrict__ out) {
    extern __shared__ unsigned char smem_raw[];
    unsigned long long* buf = reinterpret_cast<unsigned long long*>(smem_raw); // SCAP
    unsigned long long* lst = buf + SCAP;                                      // LISTCAP
    unsigned* hist = reinterpret_cast<unsigned*>(lst + LISTCAP);               // HBINS
    __shared__ unsigned wsum[32];
    __shared__ int s_cnt;
    __shared__ int sc[5];
    __shared__ int s_off[NCHS + 1];
    __shared__ int s_bad;

    const int tid = threadIdx.x;
    const int lane = tid & 31;
    const int wid = tid >> 5;                 // 32 warps
    const int b = blockIdx.x;

    if (tid < NCHS) s_off[tid] = g_cntc[b][tid];
    __syncthreads();
    if (tid == 0) {
        int acc = 0, bd = 0;
        for (int s2 = 0; s2 < NCHS; ++s2) {
            int c = s_off[s2];
            if (c > CHCAP) { bd = 1; c = CHCAP; }
            s_off[s2] = acc;
            acc += c;
        }
        s_off[NCHS] = acc;
        s_bad = bd || (acc > SCAP) || (acc < TOPK);
    }
    __syncthreads();
    int m = s_off[NCHS];

    if (!s_bad) {
        // parallel gather: warps spread across slice-parts -> one latency burst
        for (int s2 = wid; s2 < NCHS * 8; s2 += 32) {          // 8 warp-parts per slice
            int sl = s2 % NCHS;
            int part = s2 / NCHS;                               // 0..7
            int o0 = s_off[sl];
            int len = s_off[sl + 1] - o0;
            for (int i = part * 32 + lane; i < len; i += 256)
                buf[o0 + i] = g_bufc[b][sl][i];
        }
        __syncthreads();
    } else {
        // ---- fallback: adaptive restream of whole batch (never taken normally) ----
        if (tid == 0) s_cnt = 0;
        __syncthreads();
        unsigned thr2 = 0u;
        const float* Lb = logits + (size_t)b * NN;
        const int ngr = (NN + NT * 4 - 1) / (NT * 4);
        for (int g = 0; g < ngr; ++g) {
            int base = g * (NT * 4) + tid * 4;
            if (base < NN) {
                float4 w = *reinterpret_cast<const float4*>(Lb + base);
                unsigned ub[4] = {flipf(__float_as_uint(w.x)), flipf(__float_as_uint(w.y)),
                                  flipf(__float_as_uint(w.z)), flipf(__float_as_uint(w.w))};
                #pragma unroll
                for (int e = 0; e < 4; ++e)
                    if (ub[e] >= thr2) append_smem(buf, &s_cnt, ub[e], base + e);
            }
            __syncthreads();
            if (s_cnt > SCAP - NT * 4) {
                run_select(buf, lst, hist, wsum, sc, min(s_cnt, SCAP), TSEL);
                int mm = min(sc[3], LISTCAP);
                for (int i = tid; i < mm; i += NT) buf[i] = lst[i];
                __syncthreads();
                if (tid == 0) s_cnt = mm;
                __syncthreads();
                thr2 = sc[2] ? (((unsigned)sc[0] << 21) | ((unsigned)sc[1] << 10))
                             : ((unsigned)sc[0] << 21);
            }
        }
        m = min(s_cnt, SCAP);
    }

    // prune to ~TSEL best (forced sub-bin refine keeps msel ~= TSEL)
    run_select(buf, lst, hist, wsum, sc, m, TSEL);
    int msel = min(sc[3], LISTCAP);

    // sigmoid rank keys: score desc, index asc
    for (int i = tid; i < msel; i += NT) {
        unsigned long long k = lst[i];
        unsigned u = (unsigned)(k >> 32);
        unsigned idx = (unsigned)k;
        float s = sigmoid_ref(__uint_as_float(unflipf(u)));
        lst[i] = ((unsigned long long)__float_as_uint(s) << 32) |
                 (unsigned)(0xFFFFFFFFu - idx);
    }
    __syncthreads();

    if (msel <= SORTN) {
        // ---- bitonic sort SORTN keys descending; rank == index ----
        for (int i = msel + tid; i < SORTN; i += NT) lst[i] = 0ull;  // pad: smallest
        __syncthreads();
        for (int k = 2; k <= SORTN; k <<= 1) {
            for (int j = k >> 1; j > 0; j >>= 1) {
                int i = tid;
                if (i < SORTN) {
                    int ixj = i ^ j;
                    if (ixj > i) {
                        unsigned long long a = lst[i], c = lst[ixj];
                        bool up = ((i & k) == 0);                 // descending blocks
                        if (up ? (a < c) : (a > c)) { lst[i] = c; lst[ixj] = a; }
                    }
                }
                __syncthreads();
            }
        }
        if (tid < TOPK) {
            unsigned long long k = lst[tid];
            unsigned idx = 0xFFFFFFFFu - (unsigned)k;
            float s = __uint_as_float((unsigned)(k >> 32));
            int q = (int)(idx / NC);
            int c = (int)(idx - (unsigned)q * NC);
            size_t o = (size_t)b * TOPK + (size_t)tid;
            out[o] = (float)c;                                   // labels
            float4 bx = *reinterpret_cast<const float4*>(
                boxes + ((size_t)b * NQ + (size_t)q) * 4);
            float4 xy;
            xy.x = bx.x - 0.5f * bx.z;
            xy.y = bx.y - 0.5f * bx.w;
            xy.z = bx.x + 0.5f * bx.z;
            xy.w = bx.y + 0.5f * bx.w;
            *reinterpret_cast<float4*>(out + (size_t)NB * TOPK + o * 4) = xy;  // boxes
            out[(size_t)NB * TOPK * 5 + o] = s;                  // scores
        }
    } else {
        // ---- guard path (never taken normally): O(m^2) rank by counting ----
        for (int i = tid; i < msel; i += NT) {
            unsigned long long k = lst[i];
            int r = 0;
            for (int j = 0; j < msel; ++j) r += (lst[j] > k) ? 1 : 0;
            if (r < TOPK) {
                unsigned idx = 0xFFFFFFFFu - (unsigned)k;
                float s = __uint_as_float((unsigned)(k >> 32));
                int q = (int)(idx / NC);
                int c = (int)(idx - (unsigned)q * NC);
                size_t o = (size_t)b * TOPK + (size_t)r;
                out[o] = (float)c;
                float4 bx = *reinterpret_cast<const float4*>(
                    boxes + ((size_t)b * NQ + (size_t)q) * 4);
                float4 xy;
                xy.x = bx.x - 0.5f * bx.z;
                xy.y = bx.y - 0.5f * bx.w;
                xy.z = bx.x + 0.5f * bx.z;
                xy.w = bx.y + 0.5f * bx.w;
                *reinterpret_cast<float4*>(out + (size_t)NB * TOPK + o * 4) = xy;
                out[(size_t)NB * TOPK * 5 + o] = s;
            }
        }
    }
}

extern "C" void kernel_launch(void* const* d_in, const int* in_sizes, int n_in,
                              void* d_out, int out_size) {
    const float* logits = (const float*)d_in[0];
    const float* boxes = (const float*)d_in[1];
    size_t smem = (size_t)SCAP * 8 + (size_t)LISTCAP * 8 + (size_t)HBINS * 4; // 73728 B
    cudaFuncSetAttribute(select_kernel,
                         cudaFuncAttributeMaxDynamicSharedMemorySize, (int)smem);
    dim3 sg(NCHS, NB, 1);
    stream_kernel<<<sg, ST>>>(logits);
    select_kernel<<<NB, NT, smem>>>(logits, boxes, (float*)d_out);
}

// round 12
// speedup vs baseline: 2.3288x; 1.1429x over previous
#include <cuda_runtime.h>
#include <math_constants.h>

#define NB 256
#define NQ 1000
#define NC 80
#define NN 80000          // NQ * NC per batch
#define TOPK 300
#define NT 1024           // select kernel threads
#define ST 256            // stream kernel threads
#define NCHS 5            // chunks per batch (stream)
#define SCHS 16384        // elements per chunk (2 rounds of 8 float4/thread)
#define CHCAP 1024        // per-chunk survivor slice capacity
#define SCAP 6144         // smem candidate buffer entries (u64, fallback only)
#define LISTCAP 2048
#define HBINS 2048
#define TSEL 384          // fallback selection rank
#define REFINE_AT 448     // fallback: force sub-bin refine above this
#define SORTN 1024        // bitonic sort size
#define THRF 2.42f        // fixed stream threshold (~620 survivors/batch on N(0,1));
                          // m<300 or m>1024 triggers the exact fallback path

// ---------------- global scratch (static __device__, no allocs) ----------------
__device__ unsigned long long g_bufc[NB][NCHS][CHCAP];  // per-chunk survivor slices
__device__ int g_cntc[NB][NCHS];                        // per-chunk counts (plain stores)

// ---------- monotone float<->uint mapping ----------
__device__ __forceinline__ unsigned flipf(unsigned b) {
    return (b & 0x80000000u) ? ~b : (b | 0x80000000u);
}
__device__ __forceinline__ unsigned unflipf(unsigned u) {
    return (u & 0x80000000u) ? (u & 0x7FFFFFFFu) : ~u;
}

// ---------- sigmoid matching XLA: logistic(x) = 0.5 + 0.5*tanh(0.5*x) ----------
__device__ __forceinline__ float sigmoid_ref(float x) {
    float hx = __fmul_rn(0.5f, x);
    float ax = fabsf(hx);
    float xc = fminf(fmaxf(hx, -9.0f), 9.0f);
    float x2 = __fmul_rn(xc, xc);
    float p = -2.76076847742355e-16f;
    p = fmaf(x2, p, 2.00018790482477e-13f);
    p = fmaf(x2, p, -8.60467152213735e-11f);
    p = fmaf(x2, p, 5.12229709037114e-08f);
    p = fmaf(x2, p, 1.48572235717979e-05f);
    p = fmaf(x2, p, 6.37261928875436e-04f);
    p = fmaf(x2, p, 4.89352455891786e-03f);
    p = __fmul_rn(xc, p);
    float q = 1.19825839466702e-06f;
    q = fmaf(x2, q, 1.18534705686654e-04f);
    q = fmaf(x2, q, 2.26843463243900e-03f);
    q = fmaf(x2, q, 4.89352518554385e-03f);
    float t = __fdiv_rn(p, q);
    t = (ax < 4e-4f) ? hx : t;
    return __fadd_rn(__fmul_rn(0.5f, t), 0.5f);
}

// ================= 1024-thread suffix scan over 2048 bins (fallback only) =================
__device__ __forceinline__ void suffix_scan1024(unsigned* hist, unsigned* wsum) {
    const int tid = threadIdx.x;
    const int lane = tid & 31;
    const int w = tid >> 5;
    unsigned x0 = hist[2047 - 2 * tid];
    unsigned x1 = hist[2046 - 2 * tid];
    unsigned s = x0 + x1;
    unsigned incl = s;
    #pragma unroll
    for (int o = 1; o < 32; o <<= 1) {
        unsigned v = __shfl_up_sync(0xFFFFFFFFu, incl, o);
        if (lane >= o) incl += v;
    }
    if (lane == 31) wsum[w] = incl;
    unsigned excl_lane = incl - s;
    __syncthreads();
    if (tid < 32) {
        unsigned v = wsum[tid];
        unsigned wincl = v;
        #pragma unroll
        for (int o = 1; o < 32; o <<= 1) {
            unsigned t2 = __shfl_up_sync(0xFFFFFFFFu, wincl, o);
            if (tid >= o) wincl += t2;
        }
        wsum[tid] = wincl - v;
    }
    __syncthreads();
    unsigned excl = wsum[w] + excl_lane;
    hist[2047 - 2 * tid] = excl + x0;
    hist[2046 - 2 * tid] = excl + x0 + x1;
    __syncthreads();
}

// ---------- smem append (fallback path only) ----------
__device__ __forceinline__ void append_smem(unsigned long long* buf, int* cnt,
                                            unsigned ub, unsigned idx) {
    unsigned long long key = ((unsigned long long)ub << 32) | idx;
    unsigned mask = __activemask();
    int lane = threadIdx.x & 31;
    int leader = __ffs(mask) - 1;
    int pos = 0;
    if (lane == leader) pos = atomicAdd(cnt, __popc(mask));
    pos = __shfl_sync(mask, pos, leader) + __popc(mask & ((1u << lane) - 1u));
    if (pos < SCAP) buf[pos] = key;
}

// ---------- 1024-thread histogram radix-select (fallback only) ----------
__device__ void run_select(unsigned long long* buf, unsigned long long* lst,
                           unsigned* hist, unsigned* wsum, int* sc, int n, int target) {
    const int tid = threadIdx.x;
    if (n <= target) {
        if (tid == 0) { sc[0] = 0; sc[1] = 0; sc[2] = 0; sc[3] = n; }
        __syncthreads();
        for (int i = tid; i < n; i += NT) lst[i] = buf[i];
        __syncthreads();
        return;
    }
    hist[tid] = 0; hist[tid + NT] = 0;
    __syncthreads();
    for (int i = tid; i < n; i += NT)
        atomicAdd(&hist[(unsigned)(buf[i] >> 53)], 1u);
    __syncthreads();
    suffix_scan1024(hist, wsum);
    {
        unsigned s0 = hist[tid];
        unsigned s0n = (tid + 1 < HBINS) ? hist[tid + 1] : 0u;
        if (s0 >= (unsigned)target && s0n < (unsigned)target) { sc[0] = tid; sc[4] = (int)s0n; }
        unsigned s1 = hist[tid + NT];
        unsigned s1n = (tid + NT + 1 < HBINS) ? hist[tid + NT + 1] : 0u;
        if (s1 >= (unsigned)target && s1n < (unsigned)target) { sc[0] = tid + NT; sc[4] = (int)s1n; }
    }
    if (tid == 0) { sc[2] = 0; sc[3] = 0; }
    __syncthreads();
    const int B = sc[0];
    const int nAbove = sc[4];
    const int wouldSel = (int)hist[B];
    int refined = 0, B2 = 0;
    if (wouldSel > REFINE_AT) {
        __syncthreads();
        hist[tid] = 0; hist[tid + NT] = 0;
        __syncthreads();
        for (int i = tid; i < n; i += NT) {
            unsigned long long k = buf[i];
            if ((unsigned)(k >> 53) == (unsigned)B)
                atomicAdd(&hist[(unsigned)(k >> 42) & 0x7FFu], 1u);
        }
        __syncthreads();
        suffix_scan1024(hist, wsum);
        int extra = target - nAbove;
        {
            unsigned s0 = hist[tid];
            unsigned s0n = (tid + 1 < HBINS) ? hist[tid + 1] : 0u;
            if (s0 >= (unsigned)extra && s0n < (unsigned)extra) sc[1] = tid;
            unsigned s1 = hist[tid + NT];
            unsigned s1n = (tid + NT + 1 < HBINS) ? hist[tid + NT + 1] : 0u;
            if (s1 >= (unsigned)extra && s1n < (unsigned)extra) sc[1] = tid + NT;
        }
        if (tid == 0) sc[2] = 1;
        __syncthreads();
        refined = 1;
        B2 = sc[1];
    }
    for (int i = tid; i < n; i += NT) {
        unsigned long long k = buf[i];
        unsigned bin = (unsigned)(k >> 53);
        bool sel = (bin > (unsigned)B) ||
                   (bin == (unsigned)B &&
                    (!refined || (((unsigned)(k >> 42) & 0x7FFu) >= (unsigned)B2)));
        if (sel) {
            int p = atomicAdd(&sc[3], 1);
            if (p < LISTCAP) lst[p] = k;
        }
    }
    __syncthreads();
}

// ================= kernel B: lean full-bandwidth filter stream =================
extern "C" __global__ void __launch_bounds__(ST, 4)
stream_kernel(const float* __restrict__ logits) {
    __shared__ unsigned long long skeys[CHCAP];
    __shared__ int s_cnt;

    const int tid = threadIdx.x;
    const int lane = tid & 31;
    const int chunk = blockIdx.x;          // 0..NCHS-1
    const int b = blockIdx.y;              // 0..NB-1
    const float* Lp = logits + (size_t)b * NN + chunk * SCHS;
    const int rem = NN - chunk * SCHS;
    const unsigned ltmask = (1u << lane) - 1u;

    if (tid == 0) s_cnt = 0;
    __syncthreads();

    #pragma unroll
    for (int rd = 0; rd < 2; ++rd) {       // 2 rounds x 8 in-flight LDG.128
        const int robase = rd * (ST * 4 * 8);
        float4 v[8];
        bool ok[8];
        #pragma unroll
        for (int i = 0; i < 8; ++i) {
            int off = robase + i * (ST * 4) + tid * 4;
            ok[i] = off < rem;
            if (ok[i]) v[i] = __ldcs(reinterpret_cast<const float4*>(Lp + off));
        }
        #pragma unroll
        for (int i = 0; i < 8; ++i) {
            float4 w = v[i];
            float gmax = ok[i] ? fmaxf(fmaxf(w.x, w.y), fmaxf(w.z, w.w)) : -CUDART_INF_F;
            if (__any_sync(0xFFFFFFFFu, gmax >= THRF)) {
                int base = chunk * SCHS + robase + i * (ST * 4) + tid * 4;
                bool c0 = ok[i] && (w.x >= THRF);
                bool c1 = ok[i] && (w.y >= THRF);
                bool c2 = ok[i] && (w.z >= THRF);
                bool c3 = ok[i] && (w.w >= THRF);
                unsigned m0 = __ballot_sync(0xFFFFFFFFu, c0);
                unsigned m1 = __ballot_sync(0xFFFFFFFFu, c1);
                unsigned m2 = __ballot_sync(0xFFFFFFFFu, c2);
                unsigned m3 = __ballot_sync(0xFFFFFFFFu, c3);
                int tot = __popc(m0) + __popc(m1) + __popc(m2) + __popc(m3);
                int wb = 0;
                if (lane == 0) wb = atomicAdd(&s_cnt, tot);
                wb = __shfl_sync(0xFFFFFFFFu, wb, 0);
                int p = wb;
                if (c0) {
                    int ix = p + __popc(m0 & ltmask);
                    if (ix < CHCAP) skeys[ix] = ((unsigned long long)flipf(__float_as_uint(w.x)) << 32) | (unsigned)base;
                }
                p += __popc(m0);
                if (c1) {
                    int ix = p + __popc(m1 & ltmask);
                    if (ix < CHCAP) skeys[ix] = ((unsigned long long)flipf(__float_as_uint(w.y)) << 32) | (unsigned)(base + 1);
                }
                p += __popc(m1);
                if (c2) {
                    int ix = p + __popc(m2 & ltmask);
                    if (ix < CHCAP) skeys[ix] = ((unsigned long long)flipf(__float_as_uint(w.z)) << 32) | (unsigned)(base + 2);
                }
                p += __popc(m2);
                if (c3) {
                    int ix = p + __popc(m3 & ltmask);
                    if (ix < CHCAP) skeys[ix] = ((unsigned long long)flipf(__float_as_uint(w.w)) << 32) | (unsigned)(base + 3);
                }
            }
        }
    }
    __syncthreads();
    const int cn = s_cnt;
    for (int i = tid; i < min(cn, CHCAP); i += ST)
        g_bufc[b][chunk][i] = skeys[i];
    if (tid == 0) g_cntc[b][chunk] = cn;      // raw count (overflow detect)
}

// ================= kernel C: fused gather+sigmoid -> bitonic sort -> write =================
extern "C" __global__ void __launch_bounds__(NT)
select_kernel(const float* __restrict__ logits,
              const float* __restrict__ boxes,
              float* __restrict__ out) {
    extern __shared__ unsigned char smem_raw[];
    unsigned long long* buf = reinterpret_cast<unsigned long long*>(smem_raw); // SCAP (fallback)
    unsigned long long* lst = buf + SCAP;                                      // LISTCAP
    unsigned* hist = reinterpret_cast<unsigned*>(lst + LISTCAP);               // HBINS
    __shared__ unsigned wsum[32];
    __shared__ int s_cnt;
    __shared__ int sc[5];
    __shared__ int s_off[NCHS + 1];
    __shared__ int s_bad;

    const int tid = threadIdx.x;
    const int lane = tid & 31;
    const int wid = tid >> 5;                 // 32 warps
    const int b = blockIdx.x;

    if (tid < NCHS) s_off[tid] = g_cntc[b][tid];
    __syncthreads();
    if (tid == 0) {
        int acc = 0, bd = 0;
        for (int s2 = 0; s2 < NCHS; ++s2) {
            int c = s_off[s2];
            if (c > CHCAP) { bd = 1; c = CHCAP; }
            s_off[s2] = acc;
            acc += c;
        }
        s_off[NCHS] = acc;
        s_bad = bd || (acc > SORTN) || (acc < TOPK);
    }
    __syncthreads();
    int msel;

    if (!s_bad) {
        // ---- fused gather + sigmoid rank-key build, one pass, warps across slices ----
        msel = s_off[NCHS];
        for (int s2 = wid; s2 < NCHS * 8; s2 += 32) {          // 8 warp-parts per slice
            int sl = s2 % NCHS;
            int part = s2 / NCHS;                               // 0..7
            int o0 = s_off[sl];
            int len = s_off[sl + 1] - o0;
            for (int i = part * 32 + lane; i < len; i += 256) {
                unsigned long long k = g_bufc[b][sl][i];
                unsigned u = (unsigned)(k >> 32);
                unsigned idx = (unsigned)k;
                float s = sigmoid_ref(__uint_as_float(unflipf(u)));
                lst[o0 + i] = ((unsigned long long)__float_as_uint(s) << 32) |
                              (unsigned)(0xFFFFFFFFu - idx);
            }
        }
        __syncthreads();
    } else {
        // ---- fallback: adaptive restream of whole batch (never taken normally) ----
        if (tid == 0) s_cnt = 0;
        __syncthreads();
        unsigned thr2 = 0u;
        const float* Lb = logits + (size_t)b * NN;
        const int ngr = (NN + NT * 4 - 1) / (NT * 4);
        for (int g = 0; g < ngr; ++g) {
            int base = g * (NT * 4) + tid * 4;
            if (base < NN) {
                float4 w = *reinterpret_cast<const float4*>(Lb + base);
                unsigned ub[4] = {flipf(__float_as_uint(w.x)), flipf(__float_as_uint(w.y)),
                                  flipf(__float_as_uint(w.z)), flipf(__float_as_uint(w.w))};
                #pragma unroll
                for (int e = 0; e < 4; ++e)
                    if (ub[e] >= thr2) append_smem(buf, &s_cnt, ub[e], base + e);
            }
            __syncthreads();
            if (s_cnt > SCAP - NT * 4) {
                run_select(buf, lst, hist, wsum, sc, min(s_cnt, SCAP), TSEL);
                int mm = min(sc[3], LISTCAP);
                for (int i = tid; i < mm; i += NT) buf[i] = lst[i];
                __syncthreads();
                if (tid == 0) s_cnt = mm;
                __syncthreads();
                thr2 = sc[2] ? (((unsigned)sc[0] << 21) | ((unsigned)sc[1] << 10))
                             : ((unsigned)sc[0] << 21);
            }
        }
        int m = min(s_cnt, SCAP);
        run_select(buf, lst, hist, wsum, sc, m, TSEL);
        msel = min(sc[3], LISTCAP);
        // sigmoid rank keys in place
        for (int i = tid; i < msel; i += NT) {
            unsigned long long k = lst[i];
            unsigned u = (unsigned)(k >> 32);
            unsigned idx = (unsigned)k;
            float s = sigmoid_ref(__uint_as_float(unflipf(u)));
            lst[i] = ((unsigned long long)__float_as_uint(s) << 32) |
                     (unsigned)(0xFFFFFFFFu - idx);
        }
        __syncthreads();
    }

    if (msel <= SORTN) {
        // ---- bitonic sort SORTN keys descending; rank == index ----
        for (int i = msel + tid; i < SORTN; i += NT) lst[i] = 0ull;  // pad: smallest
        __syncthreads();
        for (int k = 2; k <= SORTN; k <<= 1) {
            for (int j = k >> 1; j > 0; j >>= 1) {
                int ixj = tid ^ j;
                if (ixj > tid) {
                    unsigned long long a = lst[tid], c = lst[ixj];
                    bool up = ((tid & k) == 0);                 // descending blocks
                    if (up ? (a < c) : (a > c)) { lst[tid] = c; lst[ixj] = a; }
                }
                __syncthreads();
            }
        }
        if (tid < TOPK) {
            unsigned long long k = lst[tid];
            unsigned idx = 0xFFFFFFFFu - (unsigned)k;
            float s = __uint_as_float((unsigned)(k >> 32));
            int q = (int)(idx / NC);
            int c = (int)(idx - (unsigned)q * NC);
            size_t o = (size_t)b * TOPK + (size_t)tid;
            out[o] = (float)c;                                   // labels
            float4 bx = *reinterpret_cast<const float4*>(
                boxes + ((size_t)b * NQ + (size_t)q) * 4);
            float4 xy;
            xy.x = bx.x - 0.5f * bx.z;
            xy.y = bx.y - 0.5f * bx.w;
            xy.z = bx.x + 0.5f * bx.z;
            xy.w = bx.y + 0.5f * bx.w;
            *reinterpret_cast<float4*>(out + (size_t)NB * TOPK + o * 4) = xy;  // boxes
            out[(size_t)NB * TOPK * 5 + o] = s;                  // scores
        }
    } else {
        // ---- guard path (never taken normally): O(m^2) rank by counting ----
        for (int i = tid; i < msel; i += NT) {
            unsigned long long k = lst[i];
            int r = 0;
            for (int j = 0; j < msel; ++j) r += (lst[j] > k) ? 1 : 0;
            if (r < TOPK) {
                unsigned idx = 0xFFFFFFFFu - (unsigned)k;
                float s = __uint_as_float((unsigned)(k >> 32));
                int q = (int)(idx / NC);
                int c = (int)(idx - (unsigned)q * NC);
                size_t o = (size_t)b * TOPK + (size_t)r;
                out[o] = (float)c;
                float4 bx = *reinterpret_cast<const float4*>(
                    boxes + ((size_t)b * NQ + (size_t)q) * 4);
                float4 xy;
                xy.x = bx.x - 0.5f * bx.z;
                xy.y = bx.y - 0.5f * bx.w;
                xy.z = bx.x + 0.5f * bx.z;
                xy.w = bx.y + 0.5f * bx.w;
                *reinterpret_cast<float4*>(out + (size_t)NB * TOPK + o * 4) = xy;
                out[(size_t)NB * TOPK * 5 + o] = s;
            }
        }
    }
}

extern "C" void kernel_launch(void* const* d_in, const int* in_sizes, int n_in,
                              void* d_out, int out_size) {
    const float* logits = (const float*)d_in[0];
    const float* boxes = (const float*)d_in[1];
    size_t smem = (size_t)SCAP * 8 + (size_t)LISTCAP * 8 + (size_t)HBINS * 4; // 73728 B
    cudaFuncSetAttribute(select_kernel,
                         cudaFuncAttributeMaxDynamicSharedMemorySize, (int)smem);
    dim3 sg(NCHS, NB, 1);
    stream_kernel<<<sg, ST>>>(logits);
    select_kernel<<<NB, NT, smem>>>(logits, boxes, (float*)d_out);
}

// round 13
// speedup vs baseline: 2.9978x; 1.2873x over previous
#include <cuda_runtime.h>
#include <math_constants.h>

#define NB 256
#define NQ 1000
#define NC 80
#define NN 80000          // NQ * NC per batch
#define TOPK 300
#define NT 1024           // select kernel threads
#define ST 256            // stream kernel threads
#define NCHS 5            // chunks per batch (stream)
#define SCHS 16384        // elements per chunk (2 rounds of 8 float4/thread)
#define CHCAP 1024        // per-chunk survivor slice capacity
#define SCAP 6144         // smem candidate buffer entries (u64, fallback only)
#define LISTCAP 2048
#define HBINS 2048
#define TSEL 384          // fallback selection rank
#define REFINE_AT 448     // fallback: force sub-bin refine above this
#define SORTN 1024        // bitonic sort size
#define THRF 2.42f        // fixed stream threshold (~620 survivors/batch on N(0,1));
                          // m<300 or m>1024 triggers the exact fallback path

// ---------------- global scratch (static __device__, no allocs) ----------------
__device__ unsigned long long g_bufc[NB][NCHS][CHCAP];  // per-chunk survivor slices
__device__ int g_cntc[NB][NCHS];                        // per-chunk counts (plain stores)

// ---------- monotone float<->uint mapping ----------
__device__ __forceinline__ unsigned flipf(unsigned b) {
    return (b & 0x80000000u) ? ~b : (b | 0x80000000u);
}
__device__ __forceinline__ unsigned unflipf(unsigned u) {
    return (u & 0x80000000u) ? (u & 0x7FFFFFFFu) : ~u;
}

// ---------- sigmoid matching XLA: logistic(x) = 0.5 + 0.5*tanh(0.5*x) ----------
__device__ __forceinline__ float sigmoid_ref(float x) {
    float hx = __fmul_rn(0.5f, x);
    float ax = fabsf(hx);
    float xc = fminf(fmaxf(hx, -9.0f), 9.0f);
    float x2 = __fmul_rn(xc, xc);
    float p = -2.76076847742355e-16f;
    p = fmaf(x2, p, 2.00018790482477e-13f);
    p = fmaf(x2, p, -8.60467152213735e-11f);
    p = fmaf(x2, p, 5.12229709037114e-08f);
    p = fmaf(x2, p, 1.48572235717979e-05f);
    p = fmaf(x2, p, 6.37261928875436e-04f);
    p = fmaf(x2, p, 4.89352455891786e-03f);
    p = __fmul_rn(xc, p);
    float q = 1.19825839466702e-06f;
    q = fmaf(x2, q, 1.18534705686654e-04f);
    q = fmaf(x2, q, 2.26843463243900e-03f);
    q = fmaf(x2, q, 4.89352518554385e-03f);
    float t = __fdiv_rn(p, q);
    t = (ax < 4e-4f) ? hx : t;
    return __fadd_rn(__fmul_rn(0.5f, t), 0.5f);
}

// ================= 1024-thread suffix scan over 2048 bins (fallback only) =================
__device__ __forceinline__ void suffix_scan1024(unsigned* hist, unsigned* wsum) {
    const int tid = threadIdx.x;
    const int lane = tid & 31;
    const int w = tid >> 5;
    unsigned x0 = hist[2047 - 2 * tid];
    unsigned x1 = hist[2046 - 2 * tid];
    unsigned s = x0 + x1;
    unsigned incl = s;
    #pragma unroll
    for (int o = 1; o < 32; o <<= 1) {
        unsigned v = __shfl_up_sync(0xFFFFFFFFu, incl, o);
        if (lane >= o) incl += v;
    }
    if (lane == 31) wsum[w] = incl;
    unsigned excl_lane = incl - s;
    __syncthreads();
    if (tid < 32) {
        unsigned v = wsum[tid];
        unsigned wincl = v;
        #pragma unroll
        for (int o = 1; o < 32; o <<= 1) {
            unsigned t2 = __shfl_up_sync(0xFFFFFFFFu, wincl, o);
            if (tid >= o) wincl += t2;
        }
        wsum[tid] = wincl - v;
    }
    __syncthreads();
    unsigned excl = wsum[w] + excl_lane;
    hist[2047 - 2 * tid] = excl + x0;
    hist[2046 - 2 * tid] = excl + x0 + x1;
    __syncthreads();
}

// ---------- smem append (fallback path only) ----------
__device__ __forceinline__ void append_smem(unsigned long long* buf, int* cnt,
                                            unsigned ub, unsigned idx) {
    unsigned long long key = ((unsigned long long)ub << 32) | idx;
    unsigned mask = __activemask();
    int lane = threadIdx.x & 31;
    int leader = __ffs(mask) - 1;
    int pos = 0;
    if (lane == leader) pos = atomicAdd(cnt, __popc(mask));
    pos = __shfl_sync(mask, pos, leader) + __popc(mask & ((1u << lane) - 1u));
    if (pos < SCAP) buf[pos] = key;
}

// ---------- 1024-thread histogram radix-select (fallback only) ----------
__device__ void run_select(unsigned long long* buf, unsigned long long* lst,
                           unsigned* hist, unsigned* wsum, int* sc, int n, int target) {
    const int tid = threadIdx.x;
    if (n <= target) {
        if (tid == 0) { sc[0] = 0; sc[1] = 0; sc[2] = 0; sc[3] = n; }
        __syncthreads();
        for (int i = tid; i < n; i += NT) lst[i] = buf[i];
        __syncthreads();
        return;
    }
    hist[tid] = 0; hist[tid + NT] = 0;
    __syncthreads();
    for (int i = tid; i < n; i += NT)
        atomicAdd(&hist[(unsigned)(buf[i] >> 53)], 1u);
    __syncthreads();
    suffix_scan1024(hist, wsum);
    {
        unsigned s0 = hist[tid];
        unsigned s0n = (tid + 1 < HBINS) ? hist[tid + 1] : 0u;
        if (s0 >= (unsigned)target && s0n < (unsigned)target) { sc[0] = tid; sc[4] = (int)s0n; }
        unsigned s1 = hist[tid + NT];
        unsigned s1n = (tid + NT + 1 < HBINS) ? hist[tid + NT + 1] : 0u;
        if (s1 >= (unsigned)target && s1n < (unsigned)target) { sc[0] = tid + NT; sc[4] = (int)s1n; }
    }
    if (tid == 0) { sc[2] = 0; sc[3] = 0; }
    __syncthreads();
    const int B = sc[0];
    const int nAbove = sc[4];
    const int wouldSel = (int)hist[B];
    int refined = 0, B2 = 0;
    if (wouldSel > REFINE_AT) {
        __syncthreads();
        hist[tid] = 0; hist[tid + NT] = 0;
        __syncthreads();
        for (int i = tid; i < n; i += NT) {
            unsigned long long k = buf[i];
            if ((unsigned)(k >> 53) == (unsigned)B)
                atomicAdd(&hist[(unsigned)(k >> 42) & 0x7FFu], 1u);
        }
        __syncthreads();
        suffix_scan1024(hist, wsum);
        int extra = target - nAbove;
        {
            unsigned s0 = hist[tid];
            unsigned s0n = (tid + 1 < HBINS) ? hist[tid + 1] : 0u;
            if (s0 >= (unsigned)extra && s0n < (unsigned)extra) sc[1] = tid;
            unsigned s1 = hist[tid + NT];
            unsigned s1n = (tid + NT + 1 < HBINS) ? hist[tid + NT + 1] : 0u;
            if (s1 >= (unsigned)extra && s1n < (unsigned)extra) sc[1] = tid + NT;
        }
        if (tid == 0) sc[2] = 1;
        __syncthreads();
        refined = 1;
        B2 = sc[1];
    }
    for (int i = tid; i < n; i += NT) {
        unsigned long long k = buf[i];
        unsigned bin = (unsigned)(k >> 53);
        bool sel = (bin > (unsigned)B) ||
                   (bin == (unsigned)B &&
                    (!refined || (((unsigned)(k >> 42) & 0x7FFu) >= (unsigned)B2)));
        if (sel) {
            int p = atomicAdd(&sc[3], 1);
            if (p < LISTCAP) lst[p] = k;
        }
    }
    __syncthreads();
}

// ================= kernel B: lean full-bandwidth filter stream =================
extern "C" __global__ void __launch_bounds__(ST, 4)
stream_kernel(const float* __restrict__ logits) {
    __shared__ unsigned long long skeys[CHCAP];
    __shared__ int s_cnt;

    const int tid = threadIdx.x;
    const int lane = tid & 31;
    const int chunk = blockIdx.x;          // 0..NCHS-1
    const int b = blockIdx.y;              // 0..NB-1
    const float* Lp = logits + (size_t)b * NN + chunk * SCHS;
    const int rem = NN - chunk * SCHS;
    const unsigned ltmask = (1u << lane) - 1u;

    if (tid == 0) s_cnt = 0;
    __syncthreads();

    #pragma unroll
    for (int rd = 0; rd < 2; ++rd) {       // 2 rounds x 8 in-flight LDG.128
        const int robase = rd * (ST * 4 * 8);
        float4 v[8];
        bool ok[8];
        #pragma unroll
        for (int i = 0; i < 8; ++i) {
            int off = robase + i * (ST * 4) + tid * 4;
            ok[i] = off < rem;
            if (ok[i]) v[i] = __ldcs(reinterpret_cast<const float4*>(Lp + off));
        }
        #pragma unroll
        for (int i = 0; i < 8; ++i) {
            float4 w = v[i];
            float gmax = ok[i] ? fmaxf(fmaxf(w.x, w.y), fmaxf(w.z, w.w)) : -CUDART_INF_F;
            if (__any_sync(0xFFFFFFFFu, gmax >= THRF)) {
                int base = chunk * SCHS + robase + i * (ST * 4) + tid * 4;
                bool c0 = ok[i] && (w.x >= THRF);
                bool c1 = ok[i] && (w.y >= THRF);
                bool c2 = ok[i] && (w.z >= THRF);
                bool c3 = ok[i] && (w.w >= THRF);
                unsigned m0 = __ballot_sync(0xFFFFFFFFu, c0);
                unsigned m1 = __ballot_sync(0xFFFFFFFFu, c1);
                unsigned m2 = __ballot_sync(0xFFFFFFFFu, c2);
                unsigned m3 = __ballot_sync(0xFFFFFFFFu, c3);
                int tot = __popc(m0) + __popc(m1) + __popc(m2) + __popc(m3);
                int wb = 0;
                if (lane == 0) wb = atomicAdd(&s_cnt, tot);
                wb = __shfl_sync(0xFFFFFFFFu, wb, 0);
                int p = wb;
                if (c0) {
                    int ix = p + __popc(m0 & ltmask);
                    if (ix < CHCAP) skeys[ix] = ((unsigned long long)flipf(__float_as_uint(w.x)) << 32) | (unsigned)base;
                }
                p += __popc(m0);
                if (c1) {
                    int ix = p + __popc(m1 & ltmask);
                    if (ix < CHCAP) skeys[ix] = ((unsigned long long)flipf(__float_as_uint(w.y)) << 32) | (unsigned)(base + 1);
                }
                p += __popc(m1);
                if (c2) {
                    int ix = p + __popc(m2 & ltmask);
                    if (ix < CHCAP) skeys[ix] = ((unsigned long long)flipf(__float_as_uint(w.z)) << 32) | (unsigned)(base + 2);
                }
                p += __popc(m2);
                if (c3) {
                    int ix = p + __popc(m3 & ltmask);
                    if (ix < CHCAP) skeys[ix] = ((unsigned long long)flipf(__float_as_uint(w.w)) << 32) | (unsigned)(base + 3);
                }
            }
        }
    }
    __syncthreads();
    const int cn = s_cnt;
    for (int i = tid; i < min(cn, CHCAP); i += ST)
        g_bufc[b][chunk][i] = skeys[i];
    if (tid == 0) g_cntc[b][chunk] = cn;      // raw count (overflow detect)
}

// ================= kernel C: gather+sigmoid -> hybrid bitonic sort -> write =================
extern "C" __global__ void __launch_bounds__(NT)
select_kernel(const float* __restrict__ logits,
              const float* __restrict__ boxes,
              float* __restrict__ out) {
    extern __shared__ unsigned char smem_raw[];
    unsigned long long* buf = reinterpret_cast<unsigned long long*>(smem_raw); // SCAP (fallback)
    unsigned long long* lst = buf + SCAP;                                      // LISTCAP
    unsigned* hist = reinterpret_cast<unsigned*>(lst + LISTCAP);               // HBINS
    __shared__ unsigned wsum[32];
    __shared__ int s_cnt;
    __shared__ int sc[5];
    __shared__ int s_off[NCHS + 1];
    __shared__ int s_bad;

    const int tid = threadIdx.x;
    const int lane = tid & 31;
    const int wid = tid >> 5;                 // 32 warps
    const int b = blockIdx.x;

    if (tid < NCHS) s_off[tid] = g_cntc[b][tid];
    __syncthreads();
    if (tid == 0) {
        int acc = 0, bd = 0;
        for (int s2 = 0; s2 < NCHS; ++s2) {
            int c = s_off[s2];
            if (c > CHCAP) { bd = 1; c = CHCAP; }
            s_off[s2] = acc;
            acc += c;
        }
        s_off[NCHS] = acc;
        s_bad = bd || (acc > SORTN) || (acc < TOPK);
    }
    __syncthreads();
    int msel;

    if (!s_bad) {
        // ---- fused gather + sigmoid rank-key build, one pass, warps across slices ----
        msel = s_off[NCHS];
        for (int s2 = wid; s2 < NCHS * 8; s2 += 32) {          // 8 warp-parts per slice
            int sl = s2 % NCHS;
            int part = s2 / NCHS;                               // 0..7
            int o0 = s_off[sl];
            int len = s_off[sl + 1] - o0;
            for (int i = part * 32 + lane; i < len; i += 256) {
                unsigned long long k = g_bufc[b][sl][i];
                unsigned u = (unsigned)(k >> 32);
                unsigned idx = (unsigned)k;
                float s = sigmoid_ref(__uint_as_float(unflipf(u)));
                lst[o0 + i] = ((unsigned long long)__float_as_uint(s) << 32) |
                              (unsigned)(0xFFFFFFFFu - idx);
            }
        }
        __syncthreads();
    } else {
        // ---- fallback: adaptive restream of whole batch (never taken normally) ----
        if (tid == 0) s_cnt = 0;
        __syncthreads();
        unsigned thr2 = 0u;
        const float* Lb = logits + (size_t)b * NN;
        const int ngr = (NN + NT * 4 - 1) / (NT * 4);
        for (int g = 0; g < ngr; ++g) {
            int base = g * (NT * 4) + tid * 4;
            if (base < NN) {
                float4 w = *reinterpret_cast<const float4*>(Lb + base);
                unsigned ub[4] = {flipf(__float_as_uint(w.x)), flipf(__float_as_uint(w.y)),
                                  flipf(__float_as_uint(w.z)), flipf(__float_as_uint(w.w))};
                #pragma unroll
                for (int e = 0; e < 4; ++e)
                    if (ub[e] >= thr2) append_smem(buf, &s_cnt, ub[e], base + e);
            }
            __syncthreads();
            if (s_cnt > SCAP - NT * 4) {
                run_select(buf, lst, hist, wsum, sc, min(s_cnt, SCAP), TSEL);
                int mm = min(sc[3], LISTCAP);
                for (int i = tid; i < mm; i += NT) buf[i] = lst[i];
                __syncthreads();
                if (tid == 0) s_cnt = mm;
                __syncthreads();
                thr2 = sc[2] ? (((unsigned)sc[0] << 21) | ((unsigned)sc[1] << 10))
                             : ((unsigned)sc[0] << 21);
            }
        }
        int m = min(s_cnt, SCAP);
        run_select(buf, lst, hist, wsum, sc, m, TSEL);
        msel = min(sc[3], LISTCAP);
        // sigmoid rank keys in place
        for (int i = tid; i < msel; i += NT) {
            unsigned long long k = lst[i];
            unsigned u = (unsigned)(k >> 32);
            unsigned idx = (unsigned)k;
            float s = sigmoid_ref(__uint_as_float(unflipf(u)));
            lst[i] = ((unsigned long long)__float_as_uint(s) << 32) |
                     (unsigned)(0xFFFFFFFFu - idx);
        }
        __syncthreads();
    }

    if (msel <= SORTN) {
        // ---- hybrid register/shfl bitonic sort, descending; rank == tid ----
        // key lives in a register; j<32 steps via shfl (no smem port), j>=32 via
        // symmetric smem exchange (1 STS.64 + 1 LDS.64 per thread per step).
        unsigned long long cur = (tid < msel) ? lst[tid] : 0ull;   // pad: smallest
        __syncthreads();
        #pragma unroll
        for (int k = 2; k <= SORTN; k <<= 1) {
            #pragma unroll
            for (int j = k >> 1; j > 0; j >>= 1) {
                unsigned long long partner;
                if (j < 32) {
                    partner = __shfl_xor_sync(0xFFFFFFFFu, cur, j);
                } else {
                    lst[tid] = cur;
                    __syncthreads();
                    partner = lst[tid ^ j];
                    __syncthreads();
                }
                bool keep_max = (((tid & k) == 0) == ((tid & j) == 0));
                bool pgt = partner > cur;
                cur = (keep_max == pgt) ? partner : cur;
            }
        }
        if (tid < TOPK) {
            unsigned long long k = cur;
            unsigned idx = 0xFFFFFFFFu - (unsigned)k;
            float s = __uint_as_float((unsigned)(k >> 32));
            int q = (int)(idx / NC);
            int c = (int)(idx - (unsigned)q * NC);
            size_t o = (size_t)b * TOPK + (size_t)tid;
            out[o] = (float)c;                                   // labels
            float4 bx = *reinterpret_cast<const float4*>(
                boxes + ((size_t)b * NQ + (size_t)q) * 4);
            float4 xy;
            xy.x = bx.x - 0.5f * bx.z;
            xy.y = bx.y - 0.5f * bx.w;
            xy.z = bx.x + 0.5f * bx.z;
            xy.w = bx.y + 0.5f * bx.w;
            *reinterpret_cast<float4*>(out + (size_t)NB * TOPK + o * 4) = xy;  // boxes
            out[(size_t)NB * TOPK * 5 + o] = s;                  // scores
        }
    } else {
        // ---- guard path (never taken normally): O(m^2) rank by counting ----
        for (int i = tid; i < msel; i += NT) {
            unsigned long long k = lst[i];
            int r = 0;
            for (int j = 0; j < msel; ++j) r += (lst[j] > k) ? 1 : 0;
            if (r < TOPK) {
                unsigned idx = 0xFFFFFFFFu - (unsigned)k;
                float s = __uint_as_float((unsigned)(k >> 32));
                int q = (int)(idx / NC);
                int c = (int)(idx - (unsigned)q * NC);
                size_t o = (size_t)b * TOPK + (size_t)r;
                out[o] = (float)c;
                float4 bx = *reinterpret_cast<const float4*>(
                    boxes + ((size_t)b * NQ + (size_t)q) * 4);
                float4 xy;
                xy.x = bx.x - 0.5f * bx.z;
                xy.y = bx.y - 0.5f * bx.w;
                xy.z = bx.x + 0.5f * bx.z;
                xy.w = bx.y + 0.5f * bx.w;
                *reinterpret_cast<float4*>(out + (size_t)NB * TOPK + o * 4) = xy;
                out[(size_t)NB * TOPK * 5 + o] = s;
            }
        }
    }
}

extern "C" void kernel_launch(void* const* d_in, const int* in_sizes, int n_in,
                              void* d_out, int out_size) {
    const float* logits = (const float*)d_in[0];
    const float* boxes = (const float*)d_in[1];
    size_t smem = (size_t)SCAP * 8 + (size_t)LISTCAP * 8 + (size_t)HBINS * 4; // 73728 B
    cudaFuncSetAttribute(select_kernel,
                         cudaFuncAttributeMaxDynamicSharedMemorySize, (int)smem);
    dim3 sg(NCHS, NB, 1);
    stream_kernel<<<sg, ST>>>(logits);
    select_kernel<<<NB, NT, smem>>>(logits, boxes, (float*)d_out);
}